// round 9
// baseline (speedup 1.0000x reference)
#include <cuda_runtime.h>
#include <math.h>

#define Bc   4
#define Ssz  1024
#define Hsz  1024
#define NHn  16
#define Dd   64
#define Ln   9
#define ROWS (Bc * Ssz)          // 4096
#define PADR 68                  // padded row stride (float4-aligned, 64+4)

// ---------------- scratch (device globals, no allocation) ----------------
__device__ float g_q  [ROWS * Hsz];
__device__ float g_k  [ROWS * Hsz];
__device__ float g_v  [ROWS * Hsz];
__device__ float g_ctx[ROWS * Hsz];
__device__ float g_y  [ROWS * Hsz];
__device__ float g_yn [ROWS * Hsz];
__device__ float g_span[ROWS * Ln];

// ---------------- generic tiled SGEMM: C = A[M,K] @ W[K,N] + bias (+R) ----
// BM=BN=64, BK=16, 256 threads, 4x4 per thread.
template <bool RESID>
__global__ __launch_bounds__(256)
void gemm64(const float* __restrict__ A, const float* __restrict__ W,
            const float* __restrict__ bias, const float* __restrict__ R,
            float* __restrict__ C, int M, int N, int K)
{
    __shared__ float As[16][PADR]; // transposed: As[k][m]
    __shared__ float Bs[16][64];   // Bs[k][n]

    const int tid = threadIdx.x;
    const int tx  = tid & 15;      // n-tile coord
    const int ty  = tid >> 4;      // m-tile coord
    const int bn  = blockIdx.x * 64;
    const int bm  = blockIdx.y * 64;

    const int lm  = tid >> 2;          // 0..63  (A row within tile)
    const int lk  = (tid & 3) * 4;     // 0,4,8,12 (A col quad)  -- covers BK=16 exactly
    const int lbk = tid >> 4;          // 0..15  (B row)
    const int lbn = (tid & 15) * 4;    // B col quad

    float acc[4][4];
#pragma unroll
    for (int i = 0; i < 4; i++)
#pragma unroll
        for (int j = 0; j < 4; j++) acc[i][j] = 0.0f;

    for (int kt = 0; kt < K; kt += 16) {
        float4 a4 = *(const float4*)&A[(bm + lm) * K + kt + lk];
        float4 b4 = *(const float4*)&W[(kt + lbk) * N + bn + lbn];
        __syncthreads();               // previous iteration's reads done
        As[lk + 0][lm] = a4.x;
        As[lk + 1][lm] = a4.y;
        As[lk + 2][lm] = a4.z;
        As[lk + 3][lm] = a4.w;
        *(float4*)&Bs[lbk][lbn] = b4;
        __syncthreads();

#pragma unroll
        for (int kk = 0; kk < 16; kk++) {
            float4 av = *(const float4*)&As[kk][ty * 4];
            float4 bv = *(const float4*)&Bs[kk][tx * 4];
            float a[4] = {av.x, av.y, av.z, av.w};
            float b[4] = {bv.x, bv.y, bv.z, bv.w};
#pragma unroll
            for (int i = 0; i < 4; i++)
#pragma unroll
                for (int j = 0; j < 4; j++)
                    acc[i][j] = fmaf(a[i], b[j], acc[i][j]);
        }
    }

#pragma unroll
    for (int i = 0; i < 4; i++) {
        int row = bm + ty * 4 + i;
        int col = bn + tx * 4;
        float4 out;
        float* po = (float*)&out;
#pragma unroll
        for (int j = 0; j < 4; j++) {
            float v = acc[i][j] + bias[col + j];
            if (RESID) v += R[row * N + col + j];
            po[j] = v;
        }
        *(float4*)&C[row * N + col] = out;
    }
}

// ---------------- flash attention with positional bias --------------------
// grid: (S/64, B*NH), 256 threads. Dynamic smem:
//   qs[64][68] | ks[64][68] (aliased as ps during PV) | vs[64][64]
// Tiles are 64x64: each thread loads FOUR float4s (dd = ld+16c) to cover them.
#define ATTN_SMEM_FLOATS (64 * PADR * 2 + 64 * 64)
#define ATTN_SMEM_BYTES  (ATTN_SMEM_FLOATS * 4)

__global__ __launch_bounds__(256)
void attn(const float* __restrict__ q, const float* __restrict__ k,
          const float* __restrict__ v, float* __restrict__ ctx)
{
    extern __shared__ float sm[];
    float* qs = sm;                    // [64][PADR]  (transposed: [d][m])
    float* ks = sm + 64 * PADR;        // [64][PADR]  ([d][n]; aliased as ps[n][m])
    float* vs = sm + 2 * 64 * PADR;    // [64][64]    ([n][d])

    const int bh = blockIdx.y;
    const int b  = bh >> 4;
    const int h  = bh & 15;
    const int qbase = blockIdx.x * 64;

    const int tid = threadIdx.x;
    const int tx  = tid & 15;        // n / d coord
    const int ty  = tid >> 4;        // m coord
    const int lm  = tid >> 2;        // 0..63 (row for tile loads)
    const int ld  = (tid & 3) * 4;   // base d quad; full cover via +16 steps

    const float* qp = q + ((size_t)b * Ssz) * Hsz + h * Dd;
    const float* kp = k + ((size_t)b * Ssz) * Hsz + h * Dd;
    const float* vp = v + ((size_t)b * Ssz) * Hsz + h * Dd;

    // load q tile, transposed — 4 quads per thread cover all 64 dims
#pragma unroll
    for (int c = 0; c < 4; c++) {
        int dd = ld + c * 16;
        float4 t = *(const float4*)&qp[(qbase + lm) * Hsz + dd];
        qs[(dd + 0) * PADR + lm] = t.x;
        qs[(dd + 1) * PADR + lm] = t.y;
        qs[(dd + 2) * PADR + lm] = t.z;
        qs[(dd + 3) * PADR + lm] = t.w;
    }

    float mrow[4], lrow[4], acc[4][4];
#pragma unroll
    for (int i = 0; i < 4; i++) {
        mrow[i] = -INFINITY;
        lrow[i] = 0.0f;
#pragma unroll
        for (int j = 0; j < 4; j++) acc[i][j] = 0.0f;
    }

    for (int kt = 0; kt < Ssz; kt += 64) {
        float4 kq[4], vq[4];
#pragma unroll
        for (int c = 0; c < 4; c++) {
            kq[c] = *(const float4*)&kp[(kt + lm) * Hsz + ld + c * 16];
            vq[c] = *(const float4*)&vp[(kt + lm) * Hsz + ld + c * 16];
        }
        __syncthreads();  // previous PV done reading ps/vs
#pragma unroll
        for (int c = 0; c < 4; c++) {
            int dd = ld + c * 16;
            ks[(dd + 0) * PADR + lm] = kq[c].x;
            ks[(dd + 1) * PADR + lm] = kq[c].y;
            ks[(dd + 2) * PADR + lm] = kq[c].z;
            ks[(dd + 3) * PADR + lm] = kq[c].w;
            *(float4*)&vs[lm * 64 + dd] = vq[c];
        }
        __syncthreads();

        // scores s[4][4] = q . k over all 64 dims
        float s[4][4];
#pragma unroll
        for (int i = 0; i < 4; i++)
#pragma unroll
            for (int j = 0; j < 4; j++) s[i][j] = 0.0f;

#pragma unroll 8
        for (int d = 0; d < 64; d++) {
            float4 av = *(const float4*)&qs[d * PADR + ty * 4];
            float4 bv = *(const float4*)&ks[d * PADR + tx * 4];
            float a[4] = {av.x, av.y, av.z, av.w};
            float bb[4] = {bv.x, bv.y, bv.z, bv.w};
#pragma unroll
            for (int i = 0; i < 4; i++)
#pragma unroll
                for (int j = 0; j < 4; j++)
                    s[i][j] = fmaf(a[i], bb[j], s[i][j]);
        }

        // positional bias: (s + exp(-0.1*min(dist,5))) / 8 - 0.1*dist
#pragma unroll
        for (int i = 0; i < 4; i++) {
            float qi = (float)(qbase + ty * 4 + i);
#pragma unroll
            for (int j = 0; j < 4; j++) {
                float kj = (float)(kt + tx * 4 + j);
                float dist = fabsf(qi - kj);
                float pb = __expf(-0.1f * fminf(dist, 5.0f));
                s[i][j] = (s[i][j] + pb) * 0.125f - 0.1f * dist;
            }
        }

        // online softmax update (each row shared by 16 tx lanes in one warp half)
#pragma unroll
        for (int i = 0; i < 4; i++) {
            float tmax = fmaxf(fmaxf(s[i][0], s[i][1]), fmaxf(s[i][2], s[i][3]));
#pragma unroll
            for (int off = 8; off >= 1; off >>= 1)
                tmax = fmaxf(tmax, __shfl_xor_sync(0xffffffffu, tmax, off));
            float mnew  = fmaxf(mrow[i], tmax);
            float scale = __expf(mrow[i] - mnew);
            float tsum = 0.0f;
#pragma unroll
            for (int j = 0; j < 4; j++) {
                float p = __expf(s[i][j] - mnew);
                s[i][j] = p;
                tsum += p;
            }
#pragma unroll
            for (int off = 8; off >= 1; off >>= 1)
                tsum += __shfl_xor_sync(0xffffffffu, tsum, off);
            lrow[i] = lrow[i] * scale + tsum;
            mrow[i] = mnew;
#pragma unroll
            for (int j = 0; j < 4; j++) acc[i][j] *= scale;
        }

        __syncthreads();  // all lanes done reading ks before aliasing as ps
        // write p transposed: ps[n][m]
#pragma unroll
        for (int i = 0; i < 4; i++)
#pragma unroll
            for (int j = 0; j < 4; j++)
                ks[(tx * 4 + j) * PADR + ty * 4 + i] = s[i][j];
        __syncthreads();

        // PV: acc[m][d] += p[n][m] * v[n][d]
#pragma unroll 8
        for (int n = 0; n < 64; n++) {
            float4 pm = *(const float4*)&ks[n * PADR + ty * 4];
            float4 vv = *(const float4*)&vs[n * 64 + tx * 4];
            float p[4] = {pm.x, pm.y, pm.z, pm.w};
            float w[4] = {vv.x, vv.y, vv.z, vv.w};
#pragma unroll
            for (int i = 0; i < 4; i++)
#pragma unroll
                for (int j = 0; j < 4; j++)
                    acc[i][j] = fmaf(p[i], w[j], acc[i][j]);
        }
    }

    float* cp = ctx + ((size_t)b * Ssz + qbase) * Hsz + h * Dd;
#pragma unroll
    for (int i = 0; i < 4; i++) {
        float inv = 1.0f / lrow[i];
        float4 o;
        o.x = acc[i][0] * inv;
        o.y = acc[i][1] * inv;
        o.z = acc[i][2] * inv;
        o.w = acc[i][3] * inv;
        *(float4*)&cp[(ty * 4 + i) * Hsz + tx * 4] = o;
    }
}

// ---------------- LayerNorm: one block per row ----------------------------
__global__ __launch_bounds__(256)
void lnorm(const float* __restrict__ y, const float* __restrict__ g,
           const float* __restrict__ bt, float* __restrict__ yn)
{
    const int row = blockIdx.x;
    const int tid = threadIdx.x;
    const float* yr = y + (size_t)row * Hsz;
    float* yo = yn + (size_t)row * Hsz;

    __shared__ float r1[256], r2[256];
    float s1 = 0.0f, s2 = 0.0f;
    for (int i = tid; i < Hsz; i += 256) {
        float v = yr[i];
        s1 += v;
        s2 += v * v;
    }
    r1[tid] = s1; r2[tid] = s2;
    __syncthreads();
    for (int off = 128; off > 0; off >>= 1) {
        if (tid < off) { r1[tid] += r1[tid + off]; r2[tid] += r2[tid + off]; }
        __syncthreads();
    }
    float mu  = r1[0] * (1.0f / Hsz);
    float var = r2[0] * (1.0f / Hsz) - mu * mu;
    float inv = rsqrtf(var + 1e-5f);
    for (int i = tid; i < Hsz; i += 256)
        yo[i] = (yr[i] - mu) * inv * g[i] + bt[i];
}

// ---------------- classifier: span_logits = yn @ Ws + bs ------------------
__global__ __launch_bounds__(256)
void cls(const float* __restrict__ yn, const float* __restrict__ Ws,
         const float* __restrict__ bs, float* __restrict__ span)
{
    const int row = blockIdx.x;
    const int tid = threadIdx.x;
    const float* xr = yn + (size_t)row * Hsz;

    float acc[Ln];
#pragma unroll
    for (int l = 0; l < Ln; l++) acc[l] = 0.0f;

    for (int kk = tid; kk < Hsz; kk += 256) {
        float x = xr[kk];
        const float* w = Ws + kk * Ln;
#pragma unroll
        for (int l = 0; l < Ln; l++) acc[l] = fmaf(x, w[l], acc[l]);
    }
    // warp reduce
#pragma unroll
    for (int l = 0; l < Ln; l++)
#pragma unroll
        for (int off = 16; off >= 1; off >>= 1)
            acc[l] += __shfl_xor_sync(0xffffffffu, acc[l], off);

    __shared__ float red[8][Ln];
    int warp = tid >> 5, lane = tid & 31;
    if (lane == 0)
#pragma unroll
        for (int l = 0; l < Ln; l++) red[warp][l] = acc[l];
    __syncthreads();
    if (tid < Ln) {
        float s = bs[tid];
#pragma unroll
        for (int w = 0; w < 8; w++) s += red[w][tid];
        span[(size_t)row * Ln + tid] = s;
    }
}

// ---------------- entity-bias finalize ------------------------------------
__global__ __launch_bounds__(256)
void finalize(const float* __restrict__ span, const float* __restrict__ eb,
              float* __restrict__ out)
{
    int idx = blockIdx.x * 256 + threadIdx.x;
    if (idx >= ROWS) return;
    int s = idx & (Ssz - 1);

    float vals[Ln];
#pragma unroll
    for (int l = 0; l < Ln; l++) vals[l] = span[idx * Ln + l];

    if (s > 0) {
        const float* pr = span + (idx - 1) * Ln;
        float best = pr[0];
        int bi = 0;
#pragma unroll
        for (int l = 1; l < Ln; l++)
            if (pr[l] > best) { best = pr[l]; bi = l; }   // first-max tie-break
        if (bi == 1) vals[2] += 2.0f * eb[2];             // B-PERSON -> I-PERSON
    }
#pragma unroll
    for (int l = 0; l < Ln; l++) out[idx * Ln + l] = vals[l];
}

// ---------------- launch ---------------------------------------------------
extern "C" void kernel_launch(void* const* d_in, const int* in_sizes, int n_in,
                              void* d_out, int out_size)
{
    const float* X    = (const float*)d_in[0];
    const float* Wq   = (const float*)d_in[1];
    const float* bq   = (const float*)d_in[2];
    const float* Wk   = (const float*)d_in[3];
    const float* bk   = (const float*)d_in[4];
    const float* Wv   = (const float*)d_in[5];
    const float* bv   = (const float*)d_in[6];
    const float* Wo   = (const float*)d_in[7];
    const float* bo   = (const float*)d_in[8];
    const float* ln_g = (const float*)d_in[9];
    const float* ln_b = (const float*)d_in[10];
    const float* Ws   = (const float*)d_in[11];
    const float* bs   = (const float*)d_in[12];
    const float* eb   = (const float*)d_in[13];
    // d_in[14] = rel_pos_emb (unused by forward math)
    float* out = (float*)d_out;

    float *q, *k, *v, *ctx, *y, *yn, *span;
    cudaGetSymbolAddress((void**)&q,    g_q);
    cudaGetSymbolAddress((void**)&k,    g_k);
    cudaGetSymbolAddress((void**)&v,    g_v);
    cudaGetSymbolAddress((void**)&ctx,  g_ctx);
    cudaGetSymbolAddress((void**)&y,    g_y);
    cudaGetSymbolAddress((void**)&yn,   g_yn);
    cudaGetSymbolAddress((void**)&span, g_span);

    cudaFuncSetAttribute(attn, cudaFuncAttributeMaxDynamicSharedMemorySize,
                         ATTN_SMEM_BYTES);

    dim3 gg(Hsz / 64, ROWS / 64);   // (16, 64)
    gemm64<false><<<gg, 256>>>(X, Wq, bq, nullptr, q, ROWS, Hsz, Hsz);
    gemm64<false><<<gg, 256>>>(X, Wk, bk, nullptr, k, ROWS, Hsz, Hsz);
    gemm64<false><<<gg, 256>>>(X, Wv, bv, nullptr, v, ROWS, Hsz, Hsz);

    dim3 ga(Ssz / 64, Bc * NHn);    // (16, 64)
    attn<<<ga, 256, ATTN_SMEM_BYTES>>>(q, k, v, ctx);

    gemm64<true><<<gg, 256>>>(ctx, Wo, bo, X, y, ROWS, Hsz, Hsz);

    lnorm<<<ROWS, 256>>>(y, ln_g, ln_b, yn);
    cls<<<ROWS, 256>>>(yn, Ws, bs, span);
    finalize<<<(ROWS + 255) / 256, 256>>>(span, eb, out);
}

// round 12
// speedup vs baseline: 1.6142x; 1.6142x over previous
#include <cuda_runtime.h>
#include <cuda_bf16.h>
#include <math.h>
#include <stdint.h>

#define Bc   4
#define Ssz  1024
#define Hsz  1024
#define NHn  16
#define Dd   64
#define Ln   9
#define ROWS (Bc * Ssz)          // 4096
#define PADR 68                  // attn smem row stride (float4-aligned)

// ---------------- scratch (device globals, no allocation) ----------------
__device__ float g_q  [ROWS * Hsz];
__device__ float g_k  [ROWS * Hsz];
__device__ float g_v  [ROWS * Hsz];
__device__ float g_ctx[ROWS * Hsz];
__device__ float g_y  [ROWS * Hsz];
__device__ float g_yn [ROWS * Hsz];
__device__ float g_span[ROWS * Ln];

// bf16 split operands
__device__ __nv_bfloat16 g_xh[ROWS * Hsz], g_xl[ROWS * Hsz];       // X hi/lo
__device__ __nv_bfloat16 g_ch[ROWS * Hsz], g_cl[ROWS * Hsz];       // ctx hi/lo
__device__ __nv_bfloat16 g_wth[4][Hsz * Hsz], g_wtl[4][Hsz * Hsz]; // W^T hi/lo

// ============================ helpers ====================================
__device__ __forceinline__ uint32_t smem_u32(const void* p) {
    uint32_t a;
    asm("{ .reg .u64 t; cvta.to.shared.u64 t, %1; cvt.u32.u64 %0, t; }"
        : "=r"(a) : "l"(p));
    return a;
}
#define CP_ASYNC16(sm, gm) \
    asm volatile("cp.async.cg.shared.global [%0], [%1], 16;" :: "r"(sm), "l"(gm))
#define CP_COMMIT() asm volatile("cp.async.commit_group;" ::: "memory")
#define CP_WAIT0()  asm volatile("cp.async.wait_group 0;" ::: "memory")
#define CP_WAIT1()  asm volatile("cp.async.wait_group 1;" ::: "memory")

// D(16x8,f32) += A(16x16,bf16 row) * B(16x8,bf16 col)
#define MMA16816(cc, aa, bb) \
    asm volatile("mma.sync.aligned.m16n8k16.row.col.f32.bf16.bf16.f32 " \
        "{%0,%1,%2,%3}, {%4,%5,%6,%7}, {%8,%9}, {%0,%1,%2,%3};" \
        : "+f"((cc)[0]), "+f"((cc)[1]), "+f"((cc)[2]), "+f"((cc)[3]) \
        : "r"((aa)[0]), "r"((aa)[1]), "r"((aa)[2]), "r"((aa)[3]), \
          "r"((bb)[0]), "r"((bb)[1]))

// ================= split / transpose prep kernels ========================
__global__ __launch_bounds__(256)
void split_f32(const float* __restrict__ src, __nv_bfloat16* __restrict__ hi,
               __nv_bfloat16* __restrict__ lo, int n4)
{
    int i = blockIdx.x * 256 + threadIdx.x;
    if (i >= n4) return;
    float4 x = ((const float4*)src)[i];
    __nv_bfloat16 h0 = __float2bfloat16(x.x), h1 = __float2bfloat16(x.y);
    __nv_bfloat16 h2 = __float2bfloat16(x.z), h3 = __float2bfloat16(x.w);
    __nv_bfloat16 l0 = __float2bfloat16(x.x - __bfloat162float(h0));
    __nv_bfloat16 l1 = __float2bfloat16(x.y - __bfloat162float(h1));
    __nv_bfloat16 l2 = __float2bfloat16(x.z - __bfloat162float(h2));
    __nv_bfloat16 l3 = __float2bfloat16(x.w - __bfloat162float(h3));
    ((__nv_bfloat162*)hi)[2 * i]     = __nv_bfloat162(h0, h1);
    ((__nv_bfloat162*)hi)[2 * i + 1] = __nv_bfloat162(h2, h3);
    ((__nv_bfloat162*)lo)[2 * i]     = __nv_bfloat162(l0, l1);
    ((__nv_bfloat162*)lo)[2 * i + 1] = __nv_bfloat162(l2, l3);
}

// W[k][n] (row-major KxN) -> Wt[n][k] bf16 hi/lo
__global__ __launch_bounds__(256)
void wsplit_t(const float* __restrict__ W, __nv_bfloat16* __restrict__ th,
              __nv_bfloat16* __restrict__ tl)
{
    __shared__ float t[32][33];
    int tx = threadIdx.x, ty = threadIdx.y;          // (32, 8)
    int n0 = blockIdx.x * 32, k0 = blockIdx.y * 32;
#pragma unroll
    for (int i = 0; i < 32; i += 8)
        t[ty + i][tx] = W[(size_t)(k0 + ty + i) * Hsz + n0 + tx];
    __syncthreads();
#pragma unroll
    for (int i = 0; i < 32; i += 8) {
        float v = t[tx][ty + i];                     // = W[k0+tx][n0+ty+i]
        __nv_bfloat16 h = __float2bfloat16(v);
        __nv_bfloat16 l = __float2bfloat16(v - __bfloat162float(h));
        size_t o = (size_t)(n0 + ty + i) * Hsz + k0 + tx;
        th[o] = h;
        tl[o] = l;
    }
}

// ================= mma.sync split-bf16 GEMM ==============================
// C[4096,1024] = A @ W + bias (+R), via Ah*Bh + Ah*Bl + Al*Bh (fp32 accum).
// A: hi/lo bf16 row-major [m][k]; B: W^T hi/lo bf16 [n][k].
// CTA tile 128x128, 8 warps (2m x 4n), warp tile 64x32, BK=32, double-buffered
// cp.async. smem per tile slab: 128 rows x 48-stride bf16.
#define BKc   32
#define STRs  48
#define TILEE (128 * STRs)            // 6144 bf16 per slab
#define SLAB4 (4 * TILEE)             // Ah, Al, Bh, Bl
#define GMMA_SMEM (2 * SLAB4 * 2)     // 2 buffers, bytes = 98304

template <bool RESID>
__global__ __launch_bounds__(256, 2)
void gemm_mma(const __nv_bfloat16* __restrict__ Ah, const __nv_bfloat16* __restrict__ Al,
              const __nv_bfloat16* __restrict__ Bh, const __nv_bfloat16* __restrict__ Bl,
              const float* __restrict__ bias, const float* __restrict__ R,
              float* __restrict__ C)
{
    extern __shared__ __nv_bfloat16 sb[];
    const uint32_t sbase = smem_u32(sb);

    const int tid  = threadIdx.x;
    const int lane = tid & 31;
    const int wid  = tid >> 5;
    const int wm   = wid & 1;            // 2 m-halves of 64
    const int wn   = wid >> 1;           // 4 n-quarters of 32
    const int g    = lane >> 2;          // 0..7
    const int t    = lane & 3;           // 0..3
    const int bn   = blockIdx.x * 128;
    const int bm   = blockIdx.y * 128;

    // cp.async mapping: 2 rows/thread/slab, 16B each
    const int lrow = tid >> 2;           // 0..63
    const int lc4  = tid & 3;            // 16B column (8 bf16)
    const __nv_bfloat16* gsrc[4] = {Ah, Al, Bh, Bl};
    const int gbase[4] = {bm, bm, bn, bn};

    float acc[4][4][4];
#pragma unroll
    for (int i = 0; i < 4; i++)
#pragma unroll
        for (int j = 0; j < 4; j++)
#pragma unroll
            for (int r = 0; r < 4; r++) acc[i][j][r] = 0.0f;

    // ---- issue cp.async for chunk c into buffer b ----
    auto issue = [&](int c, int b) {
#pragma unroll
        for (int s = 0; s < 4; ++s)
#pragma unroll
            for (int i = 0; i < 2; ++i) {
                int row = lrow + i * 64;
                const void* gp = &gsrc[s][(size_t)(gbase[s] + row) * Hsz + c * BKc + lc4 * 8];
                uint32_t sp = sbase + (uint32_t)(b * SLAB4 + s * TILEE + row * STRs + lc4 * 8) * 2;
                CP_ASYNC16(sp, gp);
            }
    };

    issue(0, 0);
    CP_COMMIT();

    for (int c = 0; c < Hsz / BKc; ++c) {
        if (c + 1 < Hsz / BKc) { issue(c + 1, (c + 1) & 1); CP_COMMIT(); CP_WAIT1(); }
        else                   { CP_WAIT0(); }
        __syncthreads();

        const __nv_bfloat16* As_h = sb + (c & 1) * SLAB4;
        const __nv_bfloat16* As_l = As_h + TILEE;
        const __nv_bfloat16* Bs_h = As_l + TILEE;
        const __nv_bfloat16* Bs_l = Bs_h + TILEE;

#pragma unroll
        for (int k0 = 0; k0 < BKc; k0 += 16) {
            // B fragments (hi and lo)
            uint32_t bh[4][2], bl[4][2];
#pragma unroll
            for (int nt = 0; nt < 4; ++nt) {
                int n = wn * 32 + nt * 8 + g;
                bh[nt][0] = *(const uint32_t*)&Bs_h[n * STRs + k0 + 2 * t];
                bh[nt][1] = *(const uint32_t*)&Bs_h[n * STRs + k0 + 2 * t + 8];
                bl[nt][0] = *(const uint32_t*)&Bs_l[n * STRs + k0 + 2 * t];
                bl[nt][1] = *(const uint32_t*)&Bs_l[n * STRs + k0 + 2 * t + 8];
            }
            // A-hi fragments: products Ah*Bh and Ah*Bl
            uint32_t af[4][4];
#pragma unroll
            for (int mt = 0; mt < 4; ++mt) {
                int row = wm * 64 + mt * 16 + g;
                af[mt][0] = *(const uint32_t*)&As_h[row * STRs + k0 + 2 * t];
                af[mt][1] = *(const uint32_t*)&As_h[(row + 8) * STRs + k0 + 2 * t];
                af[mt][2] = *(const uint32_t*)&As_h[row * STRs + k0 + 2 * t + 8];
                af[mt][3] = *(const uint32_t*)&As_h[(row + 8) * STRs + k0 + 2 * t + 8];
            }
#pragma unroll
            for (int mt = 0; mt < 4; ++mt)
#pragma unroll
                for (int nt = 0; nt < 4; ++nt) {
                    MMA16816(acc[mt][nt], af[mt], bh[nt]);
                    MMA16816(acc[mt][nt], af[mt], bl[nt]);
                }
            // A-lo fragments: product Al*Bh
#pragma unroll
            for (int mt = 0; mt < 4; ++mt) {
                int row = wm * 64 + mt * 16 + g;
                af[mt][0] = *(const uint32_t*)&As_l[row * STRs + k0 + 2 * t];
                af[mt][1] = *(const uint32_t*)&As_l[(row + 8) * STRs + k0 + 2 * t];
                af[mt][2] = *(const uint32_t*)&As_l[row * STRs + k0 + 2 * t + 8];
                af[mt][3] = *(const uint32_t*)&As_l[(row + 8) * STRs + k0 + 2 * t + 8];
            }
#pragma unroll
            for (int mt = 0; mt < 4; ++mt)
#pragma unroll
                for (int nt = 0; nt < 4; ++nt)
                    MMA16816(acc[mt][nt], af[mt], bh[nt]);
        }
        __syncthreads();
    }

    // ---- epilogue ----
#pragma unroll
    for (int mt = 0; mt < 4; ++mt) {
        int row = bm + wm * 64 + mt * 16 + g;
#pragma unroll
        for (int nt = 0; nt < 4; ++nt) {
            int col = bn + wn * 32 + nt * 8 + 2 * t;
            float b0 = bias[col], b1 = bias[col + 1];
            float v0 = acc[mt][nt][0] + b0;
            float v1 = acc[mt][nt][1] + b1;
            float v2 = acc[mt][nt][2] + b0;
            float v3 = acc[mt][nt][3] + b1;
            if (RESID) {
                const float* r0 = &R[(size_t)row * Hsz + col];
                const float* r8 = &R[(size_t)(row + 8) * Hsz + col];
                v0 += r0[0]; v1 += r0[1];
                v2 += r8[0]; v3 += r8[1];
            }
            *(float2*)&C[(size_t)row * Hsz + col]       = make_float2(v0, v1);
            *(float2*)&C[(size_t)(row + 8) * Hsz + col] = make_float2(v2, v3);
        }
    }
}

// ---------------- flash attention with positional bias (fp32) -------------
#define ATTN_SMEM_FLOATS (64 * PADR * 2 + 64 * 64)
#define ATTN_SMEM_BYTES  (ATTN_SMEM_FLOATS * 4)

__global__ __launch_bounds__(256)
void attn(const float* __restrict__ q, const float* __restrict__ k,
          const float* __restrict__ v, float* __restrict__ ctx)
{
    extern __shared__ float sm[];
    float* qs = sm;                    // [64][PADR]  ([d][m])
    float* ks = sm + 64 * PADR;        // [64][PADR]  ([d][n]; aliased as ps[n][m])
    float* vs = sm + 2 * 64 * PADR;    // [64][64]    ([n][d])

    const int bh = blockIdx.y;
    const int b  = bh >> 4;
    const int h  = bh & 15;
    const int qbase = blockIdx.x * 64;

    const int tid = threadIdx.x;
    const int tx  = tid & 15;
    const int ty  = tid >> 4;
    const int lm  = tid >> 2;
    const int ld  = (tid & 3) * 4;

    const float* qp = q + ((size_t)b * Ssz) * Hsz + h * Dd;
    const float* kp = k + ((size_t)b * Ssz) * Hsz + h * Dd;
    const float* vp = v + ((size_t)b * Ssz) * Hsz + h * Dd;

#pragma unroll
    for (int c = 0; c < 4; c++) {
        int dd = ld + c * 16;
        float4 t = *(const float4*)&qp[(qbase + lm) * Hsz + dd];
        qs[(dd + 0) * PADR + lm] = t.x;
        qs[(dd + 1) * PADR + lm] = t.y;
        qs[(dd + 2) * PADR + lm] = t.z;
        qs[(dd + 3) * PADR + lm] = t.w;
    }

    float mrow[4], lrow[4], acc[4][4];
#pragma unroll
    for (int i = 0; i < 4; i++) {
        mrow[i] = -INFINITY;
        lrow[i] = 0.0f;
#pragma unroll
        for (int j = 0; j < 4; j++) acc[i][j] = 0.0f;
    }

    for (int kt = 0; kt < Ssz; kt += 64) {
        float4 kq[4], vq[4];
#pragma unroll
        for (int c = 0; c < 4; c++) {
            kq[c] = *(const float4*)&kp[(kt + lm) * Hsz + ld + c * 16];
            vq[c] = *(const float4*)&vp[(kt + lm) * Hsz + ld + c * 16];
        }
        __syncthreads();
#pragma unroll
        for (int c = 0; c < 4; c++) {
            int dd = ld + c * 16;
            ks[(dd + 0) * PADR + lm] = kq[c].x;
            ks[(dd + 1) * PADR + lm] = kq[c].y;
            ks[(dd + 2) * PADR + lm] = kq[c].z;
            ks[(dd + 3) * PADR + lm] = kq[c].w;
            *(float4*)&vs[lm * 64 + dd] = vq[c];
        }
        __syncthreads();

        float s[4][4];
#pragma unroll
        for (int i = 0; i < 4; i++)
#pragma unroll
            for (int j = 0; j < 4; j++) s[i][j] = 0.0f;

#pragma unroll 8
        for (int d = 0; d < 64; d++) {
            float4 av = *(const float4*)&qs[d * PADR + ty * 4];
            float4 bv = *(const float4*)&ks[d * PADR + tx * 4];
            float a[4] = {av.x, av.y, av.z, av.w};
            float bb[4] = {bv.x, bv.y, bv.z, bv.w};
#pragma unroll
            for (int i = 0; i < 4; i++)
#pragma unroll
                for (int j = 0; j < 4; j++)
                    s[i][j] = fmaf(a[i], bb[j], s[i][j]);
        }

#pragma unroll
        for (int i = 0; i < 4; i++) {
            float qi = (float)(qbase + ty * 4 + i);
#pragma unroll
            for (int j = 0; j < 4; j++) {
                float kj = (float)(kt + tx * 4 + j);
                float dist = fabsf(qi - kj);
                float pb = __expf(-0.1f * fminf(dist, 5.0f));
                s[i][j] = (s[i][j] + pb) * 0.125f - 0.1f * dist;
            }
        }

#pragma unroll
        for (int i = 0; i < 4; i++) {
            float tmax = fmaxf(fmaxf(s[i][0], s[i][1]), fmaxf(s[i][2], s[i][3]));
#pragma unroll
            for (int off = 8; off >= 1; off >>= 1)
                tmax = fmaxf(tmax, __shfl_xor_sync(0xffffffffu, tmax, off));
            float mnew  = fmaxf(mrow[i], tmax);
            float scale = __expf(mrow[i] - mnew);
            float tsum = 0.0f;
#pragma unroll
            for (int j = 0; j < 4; j++) {
                float p = __expf(s[i][j] - mnew);
                s[i][j] = p;
                tsum += p;
            }
#pragma unroll
            for (int off = 8; off >= 1; off >>= 1)
                tsum += __shfl_xor_sync(0xffffffffu, tsum, off);
            lrow[i] = lrow[i] * scale + tsum;
            mrow[i] = mnew;
#pragma unroll
            for (int j = 0; j < 4; j++) acc[i][j] *= scale;
        }

        __syncthreads();
#pragma unroll
        for (int i = 0; i < 4; i++)
#pragma unroll
            for (int j = 0; j < 4; j++)
                ks[(tx * 4 + j) * PADR + ty * 4 + i] = s[i][j];
        __syncthreads();

#pragma unroll 8
        for (int n = 0; n < 64; n++) {
            float4 pm = *(const float4*)&ks[n * PADR + ty * 4];
            float4 vv = *(const float4*)&vs[n * 64 + tx * 4];
            float p[4] = {pm.x, pm.y, pm.z, pm.w};
            float w[4] = {vv.x, vv.y, vv.z, vv.w};
#pragma unroll
            for (int i = 0; i < 4; i++)
#pragma unroll
                for (int j = 0; j < 4; j++)
                    acc[i][j] = fmaf(p[i], w[j], acc[i][j]);
        }
    }

    float* cp = ctx + ((size_t)b * Ssz + qbase) * Hsz + h * Dd;
#pragma unroll
    for (int i = 0; i < 4; i++) {
        float inv = 1.0f / lrow[i];
        float4 o;
        o.x = acc[i][0] * inv;
        o.y = acc[i][1] * inv;
        o.z = acc[i][2] * inv;
        o.w = acc[i][3] * inv;
        *(float4*)&cp[(ty * 4 + i) * Hsz + tx * 4] = o;
    }
}

// ---------------- LayerNorm ----------------------------------------------
__global__ __launch_bounds__(256)
void lnorm(const float* __restrict__ y, const float* __restrict__ g,
           const float* __restrict__ bt, float* __restrict__ yn)
{
    const int row = blockIdx.x;
    const int tid = threadIdx.x;
    const float* yr = y + (size_t)row * Hsz;
    float* yo = yn + (size_t)row * Hsz;

    __shared__ float r1[256], r2[256];
    float s1 = 0.0f, s2 = 0.0f;
    for (int i = tid; i < Hsz; i += 256) {
        float v = yr[i];
        s1 += v;
        s2 += v * v;
    }
    r1[tid] = s1; r2[tid] = s2;
    __syncthreads();
    for (int off = 128; off > 0; off >>= 1) {
        if (tid < off) { r1[tid] += r1[tid + off]; r2[tid] += r2[tid + off]; }
        __syncthreads();
    }
    float mu  = r1[0] * (1.0f / Hsz);
    float var = r2[0] * (1.0f / Hsz) - mu * mu;
    float inv = rsqrtf(var + 1e-5f);
    for (int i = tid; i < Hsz; i += 256)
        yo[i] = (yr[i] - mu) * inv * g[i] + bt[i];
}

// ---------------- classifier ----------------------------------------------
__global__ __launch_bounds__(256)
void cls(const float* __restrict__ yn, const float* __restrict__ Ws,
         const float* __restrict__ bs, float* __restrict__ span)
{
    const int row = blockIdx.x;
    const int tid = threadIdx.x;
    const float* xr = yn + (size_t)row * Hsz;

    float acc[Ln];
#pragma unroll
    for (int l = 0; l < Ln; l++) acc[l] = 0.0f;

    for (int kk = tid; kk < Hsz; kk += 256) {
        float x = xr[kk];
        const float* w = Ws + kk * Ln;
#pragma unroll
        for (int l = 0; l < Ln; l++) acc[l] = fmaf(x, w[l], acc[l]);
    }
#pragma unroll
    for (int l = 0; l < Ln; l++)
#pragma unroll
        for (int off = 16; off >= 1; off >>= 1)
            acc[l] += __shfl_xor_sync(0xffffffffu, acc[l], off);

    __shared__ float red[8][Ln];
    int warp = tid >> 5, lane = tid & 31;
    if (lane == 0)
#pragma unroll
        for (int l = 0; l < Ln; l++) red[warp][l] = acc[l];
    __syncthreads();
    if (tid < Ln) {
        float s = bs[tid];
#pragma unroll
        for (int w = 0; w < 8; w++) s += red[w][tid];
        span[(size_t)row * Ln + tid] = s;
    }
}

// ---------------- entity-bias finalize ------------------------------------
__global__ __launch_bounds__(256)
void finalize(const float* __restrict__ span, const float* __restrict__ eb,
              float* __restrict__ out)
{
    int idx = blockIdx.x * 256 + threadIdx.x;
    if (idx >= ROWS) return;
    int s = idx & (Ssz - 1);

    float vals[Ln];
#pragma unroll
    for (int l = 0; l < Ln; l++) vals[l] = span[idx * Ln + l];

    if (s > 0) {
        const float* pr = span + (idx - 1) * Ln;
        float best = pr[0];
        int bi = 0;
#pragma unroll
        for (int l = 1; l < Ln; l++)
            if (pr[l] > best) { best = pr[l]; bi = l; }
        if (bi == 1) vals[2] += 2.0f * eb[2];
    }
#pragma unroll
    for (int l = 0; l < Ln; l++) out[idx * Ln + l] = vals[l];
}

// ---------------- launch ---------------------------------------------------
extern "C" void kernel_launch(void* const* d_in, const int* in_sizes, int n_in,
                              void* d_out, int out_size)
{
    const float* X    = (const float*)d_in[0];
    const float* Wq   = (const float*)d_in[1];
    const float* bq   = (const float*)d_in[2];
    const float* Wk   = (const float*)d_in[3];
    const float* bk   = (const float*)d_in[4];
    const float* Wv   = (const float*)d_in[5];
    const float* bv   = (const float*)d_in[6];
    const float* Wo   = (const float*)d_in[7];
    const float* bo   = (const float*)d_in[8];
    const float* ln_g = (const float*)d_in[9];
    const float* ln_b = (const float*)d_in[10];
    const float* Ws   = (const float*)d_in[11];
    const float* bs   = (const float*)d_in[12];
    const float* eb   = (const float*)d_in[13];
    float* out = (float*)d_out;

    float *q, *k, *v, *ctx, *y, *yn, *span;
    cudaGetSymbolAddress((void**)&q,    g_q);
    cudaGetSymbolAddress((void**)&k,    g_k);
    cudaGetSymbolAddress((void**)&v,    g_v);
    cudaGetSymbolAddress((void**)&ctx,  g_ctx);
    cudaGetSymbolAddress((void**)&y,    g_y);
    cudaGetSymbolAddress((void**)&yn,   g_yn);
    cudaGetSymbolAddress((void**)&span, g_span);

    __nv_bfloat16 *xh, *xl, *ch, *cl, *wth, *wtl;
    cudaGetSymbolAddress((void**)&xh,  g_xh);
    cudaGetSymbolAddress((void**)&xl,  g_xl);
    cudaGetSymbolAddress((void**)&ch,  g_ch);
    cudaGetSymbolAddress((void**)&cl,  g_cl);
    cudaGetSymbolAddress((void**)&wth, g_wth);
    cudaGetSymbolAddress((void**)&wtl, g_wtl);
    const size_t WSZ = (size_t)Hsz * Hsz;

    cudaFuncSetAttribute(attn, cudaFuncAttributeMaxDynamicSharedMemorySize,
                         ATTN_SMEM_BYTES);
    cudaFuncSetAttribute(gemm_mma<false>, cudaFuncAttributeMaxDynamicSharedMemorySize,
                         GMMA_SMEM);
    cudaFuncSetAttribute(gemm_mma<true>, cudaFuncAttributeMaxDynamicSharedMemorySize,
                         GMMA_SMEM);

    // --- operand prep (bf16 hi/lo split; W transposed) ---
    const int n4 = ROWS * Hsz / 4;
    split_f32<<<(n4 + 255) / 256, 256>>>(X, xh, xl, n4);
    dim3 wb(32, 8), wg(32, 32);
    wsplit_t<<<wg, wb>>>(Wq, wth + 0 * WSZ, wtl + 0 * WSZ);
    wsplit_t<<<wg, wb>>>(Wk, wth + 1 * WSZ, wtl + 1 * WSZ);
    wsplit_t<<<wg, wb>>>(Wv, wth + 2 * WSZ, wtl + 2 * WSZ);
    wsplit_t<<<wg, wb>>>(Wo, wth + 3 * WSZ, wtl + 3 * WSZ);

    // --- projections on tensor cores (mma.sync HMMA path) ---
    dim3 gg(Hsz / 128, ROWS / 128);   // (8, 32)
    gemm_mma<false><<<gg, 256, GMMA_SMEM>>>(xh, xl, wth + 0 * WSZ, wtl + 0 * WSZ, bq, nullptr, q);
    gemm_mma<false><<<gg, 256, GMMA_SMEM>>>(xh, xl, wth + 1 * WSZ, wtl + 1 * WSZ, bk, nullptr, k);
    gemm_mma<false><<<gg, 256, GMMA_SMEM>>>(xh, xl, wth + 2 * WSZ, wtl + 2 * WSZ, bv, nullptr, v);

    dim3 ga(Ssz / 64, Bc * NHn);      // (16, 64)
    attn<<<ga, 256, ATTN_SMEM_BYTES>>>(q, k, v, ctx);

    split_f32<<<(n4 + 255) / 256, 256>>>(ctx, ch, cl, n4);
    gemm_mma<true><<<gg, 256, GMMA_SMEM>>>(ch, cl, wth + 3 * WSZ, wtl + 3 * WSZ, bo, X, y);

    lnorm<<<ROWS, 256>>>(y, ln_g, ln_b, yn);
    cls<<<ROWS, 256>>>(yn, Ws, bs, span);
    finalize<<<(ROWS + 255) / 256, 256>>>(span, eb, out);
}

// round 13
// speedup vs baseline: 2.1846x; 1.3534x over previous
#include <cuda_runtime.h>
#include <cuda_bf16.h>
#include <math.h>
#include <stdint.h>

#define Bc   4
#define Ssz  1024
#define Hsz  1024
#define NHn  16
#define Dd   64
#define Ln   9
#define ROWS (Bc * Ssz)          // 4096

// ---------------- scratch (device globals, no allocation) ----------------
__device__ float g_q  [ROWS * Hsz];
__device__ float g_k  [ROWS * Hsz];
__device__ float g_v  [ROWS * Hsz];
__device__ float g_ctx[ROWS * Hsz];
__device__ float g_y  [ROWS * Hsz];
__device__ float g_yn [ROWS * Hsz];
__device__ float g_span[ROWS * Ln];

// bf16 split operands
__device__ __nv_bfloat16 g_xh[ROWS * Hsz], g_xl[ROWS * Hsz];       // X hi/lo
__device__ __nv_bfloat16 g_ch[ROWS * Hsz], g_cl[ROWS * Hsz];       // ctx hi/lo
__device__ __nv_bfloat16 g_wth[4][Hsz * Hsz], g_wtl[4][Hsz * Hsz]; // W^T hi/lo

// ============================ helpers ====================================
__device__ __forceinline__ uint32_t smem_u32(const void* p) {
    uint32_t a;
    asm("{ .reg .u64 t; cvta.to.shared.u64 t, %1; cvt.u32.u64 %0, t; }"
        : "=r"(a) : "l"(p));
    return a;
}
#define CP_ASYNC16(sm, gm) \
    asm volatile("cp.async.cg.shared.global [%0], [%1], 16;" :: "r"(sm), "l"(gm))
#define CP_COMMIT() asm volatile("cp.async.commit_group;" ::: "memory")
#define CP_WAIT0()  asm volatile("cp.async.wait_group 0;" ::: "memory")
#define CP_WAIT1()  asm volatile("cp.async.wait_group 1;" ::: "memory")

// D(16x8,f32) += A(16x16,bf16 row) * B(16x8,bf16 col)
#define MMA16816(cc, aa, bb) \
    asm volatile("mma.sync.aligned.m16n8k16.row.col.f32.bf16.bf16.f32 " \
        "{%0,%1,%2,%3}, {%4,%5,%6,%7}, {%8,%9}, {%0,%1,%2,%3};" \
        : "+f"((cc)[0]), "+f"((cc)[1]), "+f"((cc)[2]), "+f"((cc)[3]) \
        : "r"((aa)[0]), "r"((aa)[1]), "r"((aa)[2]), "r"((aa)[3]), \
          "r"((bb)[0]), "r"((bb)[1]))

__device__ __forceinline__ uint32_t pack_bf16x2(float a, float b) {
    __nv_bfloat162 h = __floats2bfloat162_rn(a, b);
    return *(uint32_t*)&h;
}

// ================= split / transpose prep kernels ========================
__global__ __launch_bounds__(256)
void split_f32(const float* __restrict__ src, __nv_bfloat16* __restrict__ hi,
               __nv_bfloat16* __restrict__ lo, int n4)
{
    int i = blockIdx.x * 256 + threadIdx.x;
    if (i >= n4) return;
    float4 x = ((const float4*)src)[i];
    __nv_bfloat16 h0 = __float2bfloat16(x.x), h1 = __float2bfloat16(x.y);
    __nv_bfloat16 h2 = __float2bfloat16(x.z), h3 = __float2bfloat16(x.w);
    __nv_bfloat16 l0 = __float2bfloat16(x.x - __bfloat162float(h0));
    __nv_bfloat16 l1 = __float2bfloat16(x.y - __bfloat162float(h1));
    __nv_bfloat16 l2 = __float2bfloat16(x.z - __bfloat162float(h2));
    __nv_bfloat16 l3 = __float2bfloat16(x.w - __bfloat162float(h3));
    ((__nv_bfloat162*)hi)[2 * i]     = __nv_bfloat162(h0, h1);
    ((__nv_bfloat162*)hi)[2 * i + 1] = __nv_bfloat162(h2, h3);
    ((__nv_bfloat162*)lo)[2 * i]     = __nv_bfloat162(l0, l1);
    ((__nv_bfloat162*)lo)[2 * i + 1] = __nv_bfloat162(l2, l3);
}

// W[k][n] (row-major KxN) -> Wt[n][k] bf16 hi/lo
__global__ __launch_bounds__(256)
void wsplit_t(const float* __restrict__ W, __nv_bfloat16* __restrict__ th,
              __nv_bfloat16* __restrict__ tl)
{
    __shared__ float t[32][33];
    int tx = threadIdx.x, ty = threadIdx.y;          // (32, 8)
    int n0 = blockIdx.x * 32, k0 = blockIdx.y * 32;
#pragma unroll
    for (int i = 0; i < 32; i += 8)
        t[ty + i][tx] = W[(size_t)(k0 + ty + i) * Hsz + n0 + tx];
    __syncthreads();
#pragma unroll
    for (int i = 0; i < 32; i += 8) {
        float v = t[tx][ty + i];                     // = W[k0+tx][n0+ty+i]
        __nv_bfloat16 h = __float2bfloat16(v);
        __nv_bfloat16 l = __float2bfloat16(v - __bfloat162float(h));
        size_t o = (size_t)(n0 + ty + i) * Hsz + k0 + tx;
        th[o] = h;
        tl[o] = l;
    }
}

// ================= mma.sync split-bf16 GEMM (unchanged from R12) =========
#define BKc   32
#define STRs  48
#define TILEE (128 * STRs)
#define SLAB4 (4 * TILEE)
#define GMMA_SMEM (2 * SLAB4 * 2)     // 98304 bytes

template <bool RESID>
__global__ __launch_bounds__(256, 2)
void gemm_mma(const __nv_bfloat16* __restrict__ Ah, const __nv_bfloat16* __restrict__ Al,
              const __nv_bfloat16* __restrict__ Bh, const __nv_bfloat16* __restrict__ Bl,
              const float* __restrict__ bias, const float* __restrict__ R,
              float* __restrict__ C)
{
    extern __shared__ __nv_bfloat16 sb[];
    const uint32_t sbase = smem_u32(sb);

    const int tid  = threadIdx.x;
    const int lane = tid & 31;
    const int wid  = tid >> 5;
    const int wm   = wid & 1;
    const int wn   = wid >> 1;
    const int g    = lane >> 2;
    const int t    = lane & 3;
    const int bn   = blockIdx.x * 128;
    const int bm   = blockIdx.y * 128;

    const int lrow = tid >> 2;
    const int lc4  = tid & 3;
    const __nv_bfloat16* gsrc[4] = {Ah, Al, Bh, Bl};
    const int gbase[4] = {bm, bm, bn, bn};

    float acc[4][4][4];
#pragma unroll
    for (int i = 0; i < 4; i++)
#pragma unroll
        for (int j = 0; j < 4; j++)
#pragma unroll
            for (int r = 0; r < 4; r++) acc[i][j][r] = 0.0f;

    auto issue = [&](int c, int b) {
#pragma unroll
        for (int s = 0; s < 4; ++s)
#pragma unroll
            for (int i = 0; i < 2; ++i) {
                int row = lrow + i * 64;
                const void* gp = &gsrc[s][(size_t)(gbase[s] + row) * Hsz + c * BKc + lc4 * 8];
                uint32_t sp = sbase + (uint32_t)(b * SLAB4 + s * TILEE + row * STRs + lc4 * 8) * 2;
                CP_ASYNC16(sp, gp);
            }
    };

    issue(0, 0);
    CP_COMMIT();

    for (int c = 0; c < Hsz / BKc; ++c) {
        if (c + 1 < Hsz / BKc) { issue(c + 1, (c + 1) & 1); CP_COMMIT(); CP_WAIT1(); }
        else                   { CP_WAIT0(); }
        __syncthreads();

        const __nv_bfloat16* As_h = sb + (c & 1) * SLAB4;
        const __nv_bfloat16* As_l = As_h + TILEE;
        const __nv_bfloat16* Bs_h = As_l + TILEE;
        const __nv_bfloat16* Bs_l = Bs_h + TILEE;

#pragma unroll
        for (int k0 = 0; k0 < BKc; k0 += 16) {
            uint32_t bh[4][2], bl[4][2];
#pragma unroll
            for (int nt = 0; nt < 4; ++nt) {
                int n = wn * 32 + nt * 8 + g;
                bh[nt][0] = *(const uint32_t*)&Bs_h[n * STRs + k0 + 2 * t];
                bh[nt][1] = *(const uint32_t*)&Bs_h[n * STRs + k0 + 2 * t + 8];
                bl[nt][0] = *(const uint32_t*)&Bs_l[n * STRs + k0 + 2 * t];
                bl[nt][1] = *(const uint32_t*)&Bs_l[n * STRs + k0 + 2 * t + 8];
            }
            uint32_t af[4][4];
#pragma unroll
            for (int mt = 0; mt < 4; ++mt) {
                int row = wm * 64 + mt * 16 + g;
                af[mt][0] = *(const uint32_t*)&As_h[row * STRs + k0 + 2 * t];
                af[mt][1] = *(const uint32_t*)&As_h[(row + 8) * STRs + k0 + 2 * t];
                af[mt][2] = *(const uint32_t*)&As_h[row * STRs + k0 + 2 * t + 8];
                af[mt][3] = *(const uint32_t*)&As_h[(row + 8) * STRs + k0 + 2 * t + 8];
            }
#pragma unroll
            for (int mt = 0; mt < 4; ++mt)
#pragma unroll
                for (int nt = 0; nt < 4; ++nt) {
                    MMA16816(acc[mt][nt], af[mt], bh[nt]);
                    MMA16816(acc[mt][nt], af[mt], bl[nt]);
                }
#pragma unroll
            for (int mt = 0; mt < 4; ++mt) {
                int row = wm * 64 + mt * 16 + g;
                af[mt][0] = *(const uint32_t*)&As_l[row * STRs + k0 + 2 * t];
                af[mt][1] = *(const uint32_t*)&As_l[(row + 8) * STRs + k0 + 2 * t];
                af[mt][2] = *(const uint32_t*)&As_l[row * STRs + k0 + 2 * t + 8];
                af[mt][3] = *(const uint32_t*)&As_l[(row + 8) * STRs + k0 + 2 * t + 8];
            }
#pragma unroll
            for (int mt = 0; mt < 4; ++mt)
#pragma unroll
                for (int nt = 0; nt < 4; ++nt)
                    MMA16816(acc[mt][nt], af[mt], bh[nt]);
        }
        __syncthreads();
    }

#pragma unroll
    for (int mt = 0; mt < 4; ++mt) {
        int row = bm + wm * 64 + mt * 16 + g;
#pragma unroll
        for (int nt = 0; nt < 4; ++nt) {
            int col = bn + wn * 32 + nt * 8 + 2 * t;
            float b0 = bias[col], b1 = bias[col + 1];
            float v0 = acc[mt][nt][0] + b0;
            float v1 = acc[mt][nt][1] + b1;
            float v2 = acc[mt][nt][2] + b0;
            float v3 = acc[mt][nt][3] + b1;
            if (RESID) {
                const float* r0 = &R[(size_t)row * Hsz + col];
                const float* r8 = &R[(size_t)(row + 8) * Hsz + col];
                v0 += r0[0]; v1 += r0[1];
                v2 += r8[0]; v3 += r8[1];
            }
            *(float2*)&C[(size_t)row * Hsz + col]       = make_float2(v0, v1);
            *(float2*)&C[(size_t)(row + 8) * Hsz + col] = make_float2(v2, v3);
        }
    }
}

// ================= mma.sync flash attention ==============================
// CTA: 128 q-rows of one (b,h); 8 warps x m16. 16 key tiles of 64.
// QK^T and PV in split-bf16 (3 products each), fp32 accum, online softmax.
// smem (bf16): Qh[128][72] Ql[128][72] Kh[64][72] Kl[64][72] Vth[64][72] Vtl[64][72]
#define ASTR 72
#define AQ_ELE (128 * ASTR)          // 9216
#define AK_ELE (64 * ASTR)           // 4608
#define ATTN_MMA_SMEM ((2 * AQ_ELE + 4 * AK_ELE) * 2)   // 73728 bytes

__global__ __launch_bounds__(256, 2)
void attn_mma(const float* __restrict__ q, const float* __restrict__ k,
              const float* __restrict__ v, float* __restrict__ ctx)
{
    extern __shared__ __nv_bfloat16 as[];
    __nv_bfloat16* Qh = as;
    __nv_bfloat16* Ql = as + AQ_ELE;
    __nv_bfloat16* Kh = as + 2 * AQ_ELE;
    __nv_bfloat16* Kl = Kh + AK_ELE;
    __nv_bfloat16* Vth = Kl + AK_ELE;     // [d][key]
    __nv_bfloat16* Vtl = Vth + AK_ELE;

    const int bh = blockIdx.y;
    const int b  = bh >> 4;
    const int h  = bh & 15;
    const int qbase = blockIdx.x * 128;

    const int tid  = threadIdx.x;
    const int lane = tid & 31;
    const int w    = tid >> 5;
    const int g    = lane >> 2;          // 0..7 row-in-8
    const int t    = lane & 3;           // 0..3 col-pair

    const float* qp = q + ((size_t)b * Ssz) * Hsz + h * Dd;
    const float* kp = k + ((size_t)b * Ssz) * Hsz + h * Dd;
    const float* vp = v + ((size_t)b * Ssz) * Hsz + h * Dd;

    // ---- stage Q (128x64) as hi/lo bf16 ----
    for (int i = tid; i < 128 * 16; i += 256) {
        int row = i >> 4, c4 = (i & 15) * 4;
        float4 x = *(const float4*)&qp[(size_t)(qbase + row) * Hsz + c4];
        float xv[4] = {x.x, x.y, x.z, x.w};
#pragma unroll
        for (int j = 0; j < 4; ++j) {
            __nv_bfloat16 hi = __float2bfloat16(xv[j]);
            Qh[row * ASTR + c4 + j] = hi;
            Ql[row * ASTR + c4 + j] = __float2bfloat16(xv[j] - __bfloat162float(hi));
        }
    }

    float oacc[8][4];
#pragma unroll
    for (int df = 0; df < 8; ++df)
#pragma unroll
        for (int r = 0; r < 4; ++r) oacc[df][r] = 0.0f;
    float mrun[2] = {-INFINITY, -INFINITY};
    float lrun[2] = {0.0f, 0.0f};

    const int r0 = w * 16 + g;           // warp-local fragment rows r0, r0+8

    for (int kt = 0; kt < Ssz; kt += 64) {
        __syncthreads();   // prior tile fully consumed (and Q staged, 1st iter)
        // ---- stage K tile [key][d] and V tile transposed [d][key] ----
        for (int i = tid; i < 64 * 16; i += 256) {
            int row = i >> 4, c4 = (i & 15) * 4;
            float4 kx = *(const float4*)&kp[(size_t)(kt + row) * Hsz + c4];
            float4 vx = *(const float4*)&vp[(size_t)(kt + row) * Hsz + c4];
            float kv[4] = {kx.x, kx.y, kx.z, kx.w};
            float vv[4] = {vx.x, vx.y, vx.z, vx.w};
#pragma unroll
            for (int j = 0; j < 4; ++j) {
                __nv_bfloat16 hi = __float2bfloat16(kv[j]);
                Kh[row * ASTR + c4 + j] = hi;
                Kl[row * ASTR + c4 + j] = __float2bfloat16(kv[j] - __bfloat162float(hi));
                __nv_bfloat16 vh = __float2bfloat16(vv[j]);
                Vth[(c4 + j) * ASTR + row] = vh;
                Vtl[(c4 + j) * ASTR + row] = __float2bfloat16(vv[j] - __bfloat162float(vh));
            }
        }
        __syncthreads();

        // ---- S = Q K^T (split, fp32 accum): 8 n8-frags ----
        float sacc[8][4];
#pragma unroll
        for (int nf = 0; nf < 8; ++nf)
#pragma unroll
            for (int r = 0; r < 4; ++r) sacc[nf][r] = 0.0f;

#pragma unroll
        for (int kc = 0; kc < 4; ++kc) {
            const int ko = kc * 16 + 2 * t;
            uint32_t ah[4], al[4];
            ah[0] = *(const uint32_t*)&Qh[r0 * ASTR + ko];
            ah[1] = *(const uint32_t*)&Qh[(r0 + 8) * ASTR + ko];
            ah[2] = *(const uint32_t*)&Qh[r0 * ASTR + ko + 8];
            ah[3] = *(const uint32_t*)&Qh[(r0 + 8) * ASTR + ko + 8];
            al[0] = *(const uint32_t*)&Ql[r0 * ASTR + ko];
            al[1] = *(const uint32_t*)&Ql[(r0 + 8) * ASTR + ko];
            al[2] = *(const uint32_t*)&Ql[r0 * ASTR + ko + 8];
            al[3] = *(const uint32_t*)&Ql[(r0 + 8) * ASTR + ko + 8];
#pragma unroll
            for (int nf = 0; nf < 8; ++nf) {
                int n = nf * 8 + g;
                uint32_t bh2[2], bl2[2];
                bh2[0] = *(const uint32_t*)&Kh[n * ASTR + ko];
                bh2[1] = *(const uint32_t*)&Kh[n * ASTR + ko + 8];
                bl2[0] = *(const uint32_t*)&Kl[n * ASTR + ko];
                bl2[1] = *(const uint32_t*)&Kl[n * ASTR + ko + 8];
                MMA16816(sacc[nf], ah, bh2);
                MMA16816(sacc[nf], ah, bl2);
                MMA16816(sacc[nf], al, bh2);
            }
        }

        // ---- positional bias + online softmax ----
        // frag idx: 0=(g,2t) 1=(g,2t+1) 2=(g+8,2t) 3=(g+8,2t+1)
        float rmax[2] = {-INFINITY, -INFINITY};
#pragma unroll
        for (int nf = 0; nf < 8; ++nf)
#pragma unroll
            for (int e = 0; e < 4; ++e) {
                int rr = e >> 1, cc = e & 1;
                float qi = (float)(qbase + r0 + rr * 8);
                float kj = (float)(kt + nf * 8 + 2 * t + cc);
                float dist = fabsf(qi - kj);
                float pb = __expf(-0.1f * fminf(dist, 5.0f));
                float s = (sacc[nf][e] + pb) * 0.125f - 0.1f * dist;
                sacc[nf][e] = s;
                rmax[rr] = fmaxf(rmax[rr], s);
            }
#pragma unroll
        for (int rr = 0; rr < 2; ++rr) {
            rmax[rr] = fmaxf(rmax[rr], __shfl_xor_sync(0xffffffffu, rmax[rr], 1));
            rmax[rr] = fmaxf(rmax[rr], __shfl_xor_sync(0xffffffffu, rmax[rr], 2));
        }
        float mnew[2], scale[2], lsum[2] = {0.0f, 0.0f};
#pragma unroll
        for (int rr = 0; rr < 2; ++rr) {
            mnew[rr]  = fmaxf(mrun[rr], rmax[rr]);
            scale[rr] = __expf(mrun[rr] - mnew[rr]);
            mrun[rr]  = mnew[rr];
        }
#pragma unroll
        for (int nf = 0; nf < 8; ++nf)
#pragma unroll
            for (int e = 0; e < 4; ++e) {
                int rr = e >> 1;
                float p = __expf(sacc[nf][e] - mnew[rr]);
                sacc[nf][e] = p;
                lsum[rr] += p;
            }
#pragma unroll
        for (int rr = 0; rr < 2; ++rr) {
            lsum[rr] += __shfl_xor_sync(0xffffffffu, lsum[rr], 1);
            lsum[rr] += __shfl_xor_sync(0xffffffffu, lsum[rr], 2);
            lrun[rr] = lrun[rr] * scale[rr] + lsum[rr];
        }
#pragma unroll
        for (int df = 0; df < 8; ++df) {
            oacc[df][0] *= scale[0];
            oacc[df][1] *= scale[0];
            oacc[df][2] *= scale[1];
            oacc[df][3] *= scale[1];
        }

        // ---- PV: P (register A-frags, split) x V^T tiles ----
#pragma unroll
        for (int c = 0; c < 4; ++c) {
            // A-frag from S-frags 2c (k=2t,2t+1) and 2c+1 (k=2t+8,2t+9)
            uint32_t ph[4], pl[4];
            float p00 = sacc[2 * c][0],     p01 = sacc[2 * c][1];
            float p10 = sacc[2 * c][2],     p11 = sacc[2 * c][3];
            float p20 = sacc[2 * c + 1][0], p21 = sacc[2 * c + 1][1];
            float p30 = sacc[2 * c + 1][2], p31 = sacc[2 * c + 1][3];
            ph[0] = pack_bf16x2(p00, p01);
            ph[1] = pack_bf16x2(p10, p11);
            ph[2] = pack_bf16x2(p20, p21);
            ph[3] = pack_bf16x2(p30, p31);
            pl[0] = pack_bf16x2(p00 - __bfloat162float(__float2bfloat16(p00)),
                                p01 - __bfloat162float(__float2bfloat16(p01)));
            pl[1] = pack_bf16x2(p10 - __bfloat162float(__float2bfloat16(p10)),
                                p11 - __bfloat162float(__float2bfloat16(p11)));
            pl[2] = pack_bf16x2(p20 - __bfloat162float(__float2bfloat16(p20)),
                                p21 - __bfloat162float(__float2bfloat16(p21)));
            pl[3] = pack_bf16x2(p30 - __bfloat162float(__float2bfloat16(p30)),
                                p31 - __bfloat162float(__float2bfloat16(p31)));
            const int kk = c * 16 + 2 * t;
#pragma unroll
            for (int df = 0; df < 8; ++df) {
                int n = df * 8 + g;          // d index
                uint32_t bh2[2], bl2[2];
                bh2[0] = *(const uint32_t*)&Vth[n * ASTR + kk];
                bh2[1] = *(const uint32_t*)&Vth[n * ASTR + kk + 8];
                bl2[0] = *(const uint32_t*)&Vtl[n * ASTR + kk];
                bl2[1] = *(const uint32_t*)&Vtl[n * ASTR + kk + 8];
                MMA16816(oacc[df], ph, bh2);
                MMA16816(oacc[df], ph, bl2);
                MMA16816(oacc[df], pl, bh2);
            }
        }
    }

    // ---- epilogue: ctx[row][h*64 + d] = oacc / l ----
    float inv0 = 1.0f / lrun[0], inv1 = 1.0f / lrun[1];
    float* cp = ctx + ((size_t)b * Ssz + qbase + r0) * Hsz + h * Dd;
#pragma unroll
    for (int df = 0; df < 8; ++df) {
        int col = df * 8 + 2 * t;
        *(float2*)&cp[col]            = make_float2(oacc[df][0] * inv0, oacc[df][1] * inv0);
        *(float2*)&cp[8 * Hsz + col]  = make_float2(oacc[df][2] * inv1, oacc[df][3] * inv1);
    }
}

// ---------------- LayerNorm ----------------------------------------------
__global__ __launch_bounds__(256)
void lnorm(const float* __restrict__ y, const float* __restrict__ g,
           const float* __restrict__ bt, float* __restrict__ yn)
{
    const int row = blockIdx.x;
    const int tid = threadIdx.x;
    const float* yr = y + (size_t)row * Hsz;
    float* yo = yn + (size_t)row * Hsz;

    __shared__ float r1[256], r2[256];
    float s1 = 0.0f, s2 = 0.0f;
    for (int i = tid; i < Hsz; i += 256) {
        float v = yr[i];
        s1 += v;
        s2 += v * v;
    }
    r1[tid] = s1; r2[tid] = s2;
    __syncthreads();
    for (int off = 128; off > 0; off >>= 1) {
        if (tid < off) { r1[tid] += r1[tid + off]; r2[tid] += r2[tid + off]; }
        __syncthreads();
    }
    float mu  = r1[0] * (1.0f / Hsz);
    float var = r2[0] * (1.0f / Hsz) - mu * mu;
    float inv = rsqrtf(var + 1e-5f);
    for (int i = tid; i < Hsz; i += 256)
        yo[i] = (yr[i] - mu) * inv * g[i] + bt[i];
}

// ---------------- classifier ----------------------------------------------
__global__ __launch_bounds__(256)
void cls(const float* __restrict__ yn, const float* __restrict__ Ws,
         const float* __restrict__ bs, float* __restrict__ span)
{
    const int row = blockIdx.x;
    const int tid = threadIdx.x;
    const float* xr = yn + (size_t)row * Hsz;

    float acc[Ln];
#pragma unroll
    for (int l = 0; l < Ln; l++) acc[l] = 0.0f;

    for (int kk = tid; kk < Hsz; kk += 256) {
        float x = xr[kk];
        const float* w = Ws + kk * Ln;
#pragma unroll
        for (int l = 0; l < Ln; l++) acc[l] = fmaf(x, w[l], acc[l]);
    }
#pragma unroll
    for (int l = 0; l < Ln; l++)
#pragma unroll
        for (int off = 16; off >= 1; off >>= 1)
            acc[l] += __shfl_xor_sync(0xffffffffu, acc[l], off);

    __shared__ float red[8][Ln];
    int warp = tid >> 5, lane = tid & 31;
    if (lane == 0)
#pragma unroll
        for (int l = 0; l < Ln; l++) red[warp][l] = acc[l];
    __syncthreads();
    if (tid < Ln) {
        float s = bs[tid];
#pragma unroll
        for (int w = 0; w < 8; w++) s += red[w][tid];
        span[(size_t)row * Ln + tid] = s;
    }
}

// ---------------- entity-bias finalize ------------------------------------
__global__ __launch_bounds__(256)
void finalize(const float* __restrict__ span, const float* __restrict__ eb,
              float* __restrict__ out)
{
    int idx = blockIdx.x * 256 + threadIdx.x;
    if (idx >= ROWS) return;
    int s = idx & (Ssz - 1);

    float vals[Ln];
#pragma unroll
    for (int l = 0; l < Ln; l++) vals[l] = span[idx * Ln + l];

    if (s > 0) {
        const float* pr = span + (idx - 1) * Ln;
        float best = pr[0];
        int bi = 0;
#pragma unroll
        for (int l = 1; l < Ln; l++)
            if (pr[l] > best) { best = pr[l]; bi = l; }
        if (bi == 1) vals[2] += 2.0f * eb[2];
    }
#pragma unroll
    for (int l = 0; l < Ln; l++) out[idx * Ln + l] = vals[l];
}

// ---------------- launch ---------------------------------------------------
extern "C" void kernel_launch(void* const* d_in, const int* in_sizes, int n_in,
                              void* d_out, int out_size)
{
    const float* X    = (const float*)d_in[0];
    const float* Wq   = (const float*)d_in[1];
    const float* bq   = (const float*)d_in[2];
    const float* Wk   = (const float*)d_in[3];
    const float* bk   = (const float*)d_in[4];
    const float* Wv   = (const float*)d_in[5];
    const float* bv   = (const float*)d_in[6];
    const float* Wo   = (const float*)d_in[7];
    const float* bo   = (const float*)d_in[8];
    const float* ln_g = (const float*)d_in[9];
    const float* ln_b = (const float*)d_in[10];
    const float* Ws   = (const float*)d_in[11];
    const float* bs   = (const float*)d_in[12];
    const float* eb   = (const float*)d_in[13];
    float* out = (float*)d_out;

    float *q, *k, *v, *ctx, *y, *yn, *span;
    cudaGetSymbolAddress((void**)&q,    g_q);
    cudaGetSymbolAddress((void**)&k,    g_k);
    cudaGetSymbolAddress((void**)&v,    g_v);
    cudaGetSymbolAddress((void**)&ctx,  g_ctx);
    cudaGetSymbolAddress((void**)&y,    g_y);
    cudaGetSymbolAddress((void**)&yn,   g_yn);
    cudaGetSymbolAddress((void**)&span, g_span);

    __nv_bfloat16 *xh, *xl, *ch, *cl, *wth, *wtl;
    cudaGetSymbolAddress((void**)&xh,  g_xh);
    cudaGetSymbolAddress((void**)&xl,  g_xl);
    cudaGetSymbolAddress((void**)&ch,  g_ch);
    cudaGetSymbolAddress((void**)&cl,  g_cl);
    cudaGetSymbolAddress((void**)&wth, g_wth);
    cudaGetSymbolAddress((void**)&wtl, g_wtl);
    const size_t WSZ = (size_t)Hsz * Hsz;

    cudaFuncSetAttribute(attn_mma, cudaFuncAttributeMaxDynamicSharedMemorySize,
                         ATTN_MMA_SMEM);
    cudaFuncSetAttribute(gemm_mma<false>, cudaFuncAttributeMaxDynamicSharedMemorySize,
                         GMMA_SMEM);
    cudaFuncSetAttribute(gemm_mma<true>, cudaFuncAttributeMaxDynamicSharedMemorySize,
                         GMMA_SMEM);

    // --- operand prep (bf16 hi/lo split; W transposed) ---
    const int n4 = ROWS * Hsz / 4;
    split_f32<<<(n4 + 255) / 256, 256>>>(X, xh, xl, n4);
    dim3 wb(32, 8), wg(32, 32);
    wsplit_t<<<wg, wb>>>(Wq, wth + 0 * WSZ, wtl + 0 * WSZ);
    wsplit_t<<<wg, wb>>>(Wk, wth + 1 * WSZ, wtl + 1 * WSZ);
    wsplit_t<<<wg, wb>>>(Wv, wth + 2 * WSZ, wtl + 2 * WSZ);
    wsplit_t<<<wg, wb>>>(Wo, wth + 3 * WSZ, wtl + 3 * WSZ);

    // --- projections on tensor cores ---
    dim3 gg(Hsz / 128, ROWS / 128);   // (8, 32)
    gemm_mma<false><<<gg, 256, GMMA_SMEM>>>(xh, xl, wth + 0 * WSZ, wtl + 0 * WSZ, bq, nullptr, q);
    gemm_mma<false><<<gg, 256, GMMA_SMEM>>>(xh, xl, wth + 1 * WSZ, wtl + 1 * WSZ, bk, nullptr, k);
    gemm_mma<false><<<gg, 256, GMMA_SMEM>>>(xh, xl, wth + 2 * WSZ, wtl + 2 * WSZ, bv, nullptr, v);

    // --- attention on tensor cores ---
    dim3 ga(Ssz / 128, Bc * NHn);     // (8, 64)
    attn_mma<<<ga, 256, ATTN_MMA_SMEM>>>(q, k, v, ctx);

    split_f32<<<(n4 + 255) / 256, 256>>>(ctx, ch, cl, n4);
    gemm_mma<true><<<gg, 256, GMMA_SMEM>>>(ch, cl, wth + 3 * WSZ, wtl + 3 * WSZ, bo, X, y);

    lnorm<<<ROWS, 256>>>(y, ln_g, ln_b, yn);
    cls<<<ROWS, 256>>>(yn, Ws, bs, span);
    finalize<<<(ROWS + 255) / 256, 256>>>(span, eb, out);
}

// round 14
// speedup vs baseline: 2.2216x; 1.0169x over previous
#include <cuda_runtime.h>
#include <cuda_bf16.h>
#include <math.h>
#include <stdint.h>

#define Bc   4
#define Ssz  1024
#define Hsz  1024
#define NHn  16
#define Dd   64
#define Ln   9
#define ROWS (Bc * Ssz)          // 4096

// ---------------- scratch (device globals, no allocation) ----------------
__device__ float g_y  [ROWS * Hsz];
__device__ float g_span[ROWS * Ln];

// bf16 split operands
__device__ __nv_bfloat16 g_xh[ROWS * Hsz], g_xl[ROWS * Hsz];       // X hi/lo
__device__ __nv_bfloat16 g_qh[ROWS * Hsz], g_ql[ROWS * Hsz];
__device__ __nv_bfloat16 g_kh[ROWS * Hsz], g_kl[ROWS * Hsz];
__device__ __nv_bfloat16 g_vh[ROWS * Hsz], g_vl[ROWS * Hsz];
__device__ __nv_bfloat16 g_ch[ROWS * Hsz], g_cl[ROWS * Hsz];       // ctx hi/lo
__device__ __nv_bfloat16 g_wth[4][Hsz * Hsz], g_wtl[4][Hsz * Hsz]; // W^T hi/lo

// ============================ helpers ====================================
__device__ __forceinline__ uint32_t smem_u32(const void* p) {
    uint32_t a;
    asm("{ .reg .u64 t; cvta.to.shared.u64 t, %1; cvt.u32.u64 %0, t; }"
        : "=r"(a) : "l"(p));
    return a;
}
#define CP_ASYNC16(sm, gm) \
    asm volatile("cp.async.cg.shared.global [%0], [%1], 16;" :: "r"(sm), "l"(gm))
#define CP_COMMIT() asm volatile("cp.async.commit_group;" ::: "memory")
#define CP_WAIT0()  asm volatile("cp.async.wait_group 0;" ::: "memory")
#define CP_WAIT1()  asm volatile("cp.async.wait_group 1;" ::: "memory")

// D(16x8,f32) += A(16x16,bf16 row) * B(16x8,bf16 col)
#define MMA16816(cc, aa, bb) \
    asm volatile("mma.sync.aligned.m16n8k16.row.col.f32.bf16.bf16.f32 " \
        "{%0,%1,%2,%3}, {%4,%5,%6,%7}, {%8,%9}, {%0,%1,%2,%3};" \
        : "+f"((cc)[0]), "+f"((cc)[1]), "+f"((cc)[2]), "+f"((cc)[3]) \
        : "r"((aa)[0]), "r"((aa)[1]), "r"((aa)[2]), "r"((aa)[3]), \
          "r"((bb)[0]), "r"((bb)[1]))

__device__ __forceinline__ uint32_t pack_bf16x2(float a, float b) {
    __nv_bfloat162 h = __floats2bfloat162_rn(a, b);
    return *(uint32_t*)&h;
}
// split pair (a,b) -> hi uint32 / lo uint32
__device__ __forceinline__ void split_pair(float a, float b, uint32_t& hi, uint32_t& lo) {
    __nv_bfloat16 ha = __float2bfloat16(a), hb = __float2bfloat16(b);
    __nv_bfloat16 la = __float2bfloat16(a - __bfloat162float(ha));
    __nv_bfloat16 lb = __float2bfloat16(b - __bfloat162float(hb));
    __nv_bfloat162 hh(ha, hb), ll(la, lb);
    hi = *(uint32_t*)&hh;
    lo = *(uint32_t*)&ll;
}

// ================= split / transpose prep kernels ========================
__global__ __launch_bounds__(256)
void split_f32(const float* __restrict__ src, __nv_bfloat16* __restrict__ hi,
               __nv_bfloat16* __restrict__ lo, int n4)
{
    int i = blockIdx.x * 256 + threadIdx.x;
    if (i >= n4) return;
    float4 x = ((const float4*)src)[i];
    uint32_t h0, l0, h1, l1;
    split_pair(x.x, x.y, h0, l0);
    split_pair(x.z, x.w, h1, l1);
    ((uint32_t*)hi)[2 * i]     = h0;
    ((uint32_t*)hi)[2 * i + 1] = h1;
    ((uint32_t*)lo)[2 * i]     = l0;
    ((uint32_t*)lo)[2 * i + 1] = l1;
}

// W[k][n] (row-major KxN) -> Wt[n][k] bf16 hi/lo
__global__ __launch_bounds__(256)
void wsplit_t(const float* __restrict__ W, __nv_bfloat16* __restrict__ th,
              __nv_bfloat16* __restrict__ tl)
{
    __shared__ float t[32][33];
    int tx = threadIdx.x, ty = threadIdx.y;          // (32, 8)
    int n0 = blockIdx.x * 32, k0 = blockIdx.y * 32;
#pragma unroll
    for (int i = 0; i < 32; i += 8)
        t[ty + i][tx] = W[(size_t)(k0 + ty + i) * Hsz + n0 + tx];
    __syncthreads();
#pragma unroll
    for (int i = 0; i < 32; i += 8) {
        float v = t[tx][ty + i];
        __nv_bfloat16 h = __float2bfloat16(v);
        __nv_bfloat16 l = __float2bfloat16(v - __bfloat162float(h));
        size_t o = (size_t)(n0 + ty + i) * Hsz + k0 + tx;
        th[o] = h;
        tl[o] = l;
    }
}

// ================= mma.sync split-bf16 GEMM ==============================
// SPLIT=true:  write Ch/Cl split-bf16 (for q/k/v).  SPLIT=false: fp32 C (+R).
#define BKc   32
#define STRs  48
#define TILEE (128 * STRs)
#define SLAB4 (4 * TILEE)
#define GMMA_SMEM (2 * SLAB4 * 2)     // 98304 bytes

template <bool RESID, bool SPLIT>
__global__ __launch_bounds__(256, 2)
void gemm_mma(const __nv_bfloat16* __restrict__ Ah, const __nv_bfloat16* __restrict__ Al,
              const __nv_bfloat16* __restrict__ Bh, const __nv_bfloat16* __restrict__ Bl,
              const float* __restrict__ bias, const float* __restrict__ R,
              float* __restrict__ C,
              __nv_bfloat16* __restrict__ Ch, __nv_bfloat16* __restrict__ Cl)
{
    extern __shared__ __nv_bfloat16 sb[];
    const uint32_t sbase = smem_u32(sb);

    const int tid  = threadIdx.x;
    const int lane = tid & 31;
    const int wid  = tid >> 5;
    const int wm   = wid & 1;
    const int wn   = wid >> 1;
    const int g    = lane >> 2;
    const int t    = lane & 3;
    const int bn   = blockIdx.x * 128;
    const int bm   = blockIdx.y * 128;

    const int lrow = tid >> 2;
    const int lc4  = tid & 3;
    const __nv_bfloat16* gsrc[4] = {Ah, Al, Bh, Bl};
    const int gbase[4] = {bm, bm, bn, bn};

    float acc[4][4][4];
#pragma unroll
    for (int i = 0; i < 4; i++)
#pragma unroll
        for (int j = 0; j < 4; j++)
#pragma unroll
            for (int r = 0; r < 4; r++) acc[i][j][r] = 0.0f;

    auto issue = [&](int c, int b) {
#pragma unroll
        for (int s = 0; s < 4; ++s)
#pragma unroll
            for (int i = 0; i < 2; ++i) {
                int row = lrow + i * 64;
                const void* gp = &gsrc[s][(size_t)(gbase[s] + row) * Hsz + c * BKc + lc4 * 8];
                uint32_t sp = sbase + (uint32_t)(b * SLAB4 + s * TILEE + row * STRs + lc4 * 8) * 2;
                CP_ASYNC16(sp, gp);
            }
    };

    issue(0, 0);
    CP_COMMIT();

    for (int c = 0; c < Hsz / BKc; ++c) {
        if (c + 1 < Hsz / BKc) { issue(c + 1, (c + 1) & 1); CP_COMMIT(); CP_WAIT1(); }
        else                   { CP_WAIT0(); }
        __syncthreads();

        const __nv_bfloat16* As_h = sb + (c & 1) * SLAB4;
        const __nv_bfloat16* As_l = As_h + TILEE;
        const __nv_bfloat16* Bs_h = As_l + TILEE;
        const __nv_bfloat16* Bs_l = Bs_h + TILEE;

#pragma unroll
        for (int k0 = 0; k0 < BKc; k0 += 16) {
            uint32_t bh[4][2], bl[4][2];
#pragma unroll
            for (int nt = 0; nt < 4; ++nt) {
                int n = wn * 32 + nt * 8 + g;
                bh[nt][0] = *(const uint32_t*)&Bs_h[n * STRs + k0 + 2 * t];
                bh[nt][1] = *(const uint32_t*)&Bs_h[n * STRs + k0 + 2 * t + 8];
                bl[nt][0] = *(const uint32_t*)&Bs_l[n * STRs + k0 + 2 * t];
                bl[nt][1] = *(const uint32_t*)&Bs_l[n * STRs + k0 + 2 * t + 8];
            }
            uint32_t af[4][4];
#pragma unroll
            for (int mt = 0; mt < 4; ++mt) {
                int row = wm * 64 + mt * 16 + g;
                af[mt][0] = *(const uint32_t*)&As_h[row * STRs + k0 + 2 * t];
                af[mt][1] = *(const uint32_t*)&As_h[(row + 8) * STRs + k0 + 2 * t];
                af[mt][2] = *(const uint32_t*)&As_h[row * STRs + k0 + 2 * t + 8];
                af[mt][3] = *(const uint32_t*)&As_h[(row + 8) * STRs + k0 + 2 * t + 8];
            }
#pragma unroll
            for (int mt = 0; mt < 4; ++mt)
#pragma unroll
                for (int nt = 0; nt < 4; ++nt) {
                    MMA16816(acc[mt][nt], af[mt], bh[nt]);
                    MMA16816(acc[mt][nt], af[mt], bl[nt]);
                }
#pragma unroll
            for (int mt = 0; mt < 4; ++mt) {
                int row = wm * 64 + mt * 16 + g;
                af[mt][0] = *(const uint32_t*)&As_l[row * STRs + k0 + 2 * t];
                af[mt][1] = *(const uint32_t*)&As_l[(row + 8) * STRs + k0 + 2 * t];
                af[mt][2] = *(const uint32_t*)&As_l[row * STRs + k0 + 2 * t + 8];
                af[mt][3] = *(const uint32_t*)&As_l[(row + 8) * STRs + k0 + 2 * t + 8];
            }
#pragma unroll
            for (int mt = 0; mt < 4; ++mt)
#pragma unroll
                for (int nt = 0; nt < 4; ++nt)
                    MMA16816(acc[mt][nt], af[mt], bh[nt]);
        }
        __syncthreads();
    }

#pragma unroll
    for (int mt = 0; mt < 4; ++mt) {
        int row = bm + wm * 64 + mt * 16 + g;
#pragma unroll
        for (int nt = 0; nt < 4; ++nt) {
            int col = bn + wn * 32 + nt * 8 + 2 * t;
            float b0 = bias[col], b1 = bias[col + 1];
            float v0 = acc[mt][nt][0] + b0;
            float v1 = acc[mt][nt][1] + b1;
            float v2 = acc[mt][nt][2] + b0;
            float v3 = acc[mt][nt][3] + b1;
            if (SPLIT) {
                uint32_t h0, l0, h1, l1;
                split_pair(v0, v1, h0, l0);
                split_pair(v2, v3, h1, l1);
                *(uint32_t*)&Ch[(size_t)row * Hsz + col]       = h0;
                *(uint32_t*)&Cl[(size_t)row * Hsz + col]       = l0;
                *(uint32_t*)&Ch[(size_t)(row + 8) * Hsz + col] = h1;
                *(uint32_t*)&Cl[(size_t)(row + 8) * Hsz + col] = l1;
            } else {
                if (RESID) {
                    const float* r0 = &R[(size_t)row * Hsz + col];
                    const float* r8 = &R[(size_t)(row + 8) * Hsz + col];
                    v0 += r0[0]; v1 += r0[1];
                    v2 += r8[0]; v3 += r8[1];
                }
                *(float2*)&C[(size_t)row * Hsz + col]       = make_float2(v0, v1);
                *(float2*)&C[(size_t)(row + 8) * Hsz + col] = make_float2(v2, v3);
            }
        }
    }
}

// ================= mma.sync flash attention (bf16-split inputs) ==========
// Inputs pre-split bf16 (Qh/Ql/Kh/Kl/Vh/Vl, layout [b*S+row][H]).
// Staging: Q,K via cp.async; V via uint4 LDG + transposed STS (no cvt).
// Output: ctx split bf16 (Ch/Cl).
#define ASTR 72
#define AQ_ELE (128 * ASTR)
#define AK_ELE (64 * ASTR)
#define ATTN_MMA_SMEM ((2 * AQ_ELE + 4 * AK_ELE) * 2)   // 73728 bytes

__global__ __launch_bounds__(256, 2)
void attn_mma(const __nv_bfloat16* __restrict__ qh, const __nv_bfloat16* __restrict__ ql,
              const __nv_bfloat16* __restrict__ kh, const __nv_bfloat16* __restrict__ kl,
              const __nv_bfloat16* __restrict__ vh, const __nv_bfloat16* __restrict__ vl,
              __nv_bfloat16* __restrict__ ch, __nv_bfloat16* __restrict__ cl)
{
    extern __shared__ __nv_bfloat16 as[];
    __nv_bfloat16* Qh = as;
    __nv_bfloat16* Ql = as + AQ_ELE;
    __nv_bfloat16* Kh = as + 2 * AQ_ELE;
    __nv_bfloat16* Kl = Kh + AK_ELE;
    __nv_bfloat16* Vth = Kl + AK_ELE;     // [d][key]
    __nv_bfloat16* Vtl = Vth + AK_ELE;
    const uint32_t sbase = smem_u32(as);
    const uint32_t Kh_off = (uint32_t)(2 * AQ_ELE) * 2;
    const uint32_t Kl_off = Kh_off + AK_ELE * 2;

    const int bh = blockIdx.y;
    const int b  = bh >> 4;
    const int h  = bh & 15;
    const int qbase = blockIdx.x * 128;

    const int tid  = threadIdx.x;
    const int lane = tid & 31;
    const int w    = tid >> 5;
    const int g    = lane >> 2;
    const int t    = lane & 3;

    const size_t hb = ((size_t)b * Ssz) * Hsz + h * Dd;
    const __nv_bfloat16* qph = qh + hb;
    const __nv_bfloat16* qpl = ql + hb;
    const __nv_bfloat16* kph = kh + hb;
    const __nv_bfloat16* kpl = kl + hb;
    const __nv_bfloat16* vph = vh + hb;
    const __nv_bfloat16* vpl = vl + hb;

    // ---- stage Q (128x64 bf16 hi/lo) via cp.async ----
    {
        // 128 rows x 8 chunks x 2 arrays = 2048 chunks; 8 per thread
        for (int i = tid; i < 128 * 8; i += 256) {
            int row = i >> 3, c8 = (i & 7) * 8;
            CP_ASYNC16(sbase + (uint32_t)(row * ASTR + c8) * 2,
                       &qph[(size_t)(qbase + row) * Hsz + c8]);
            CP_ASYNC16(sbase + (uint32_t)(AQ_ELE + row * ASTR + c8) * 2,
                       &qpl[(size_t)(qbase + row) * Hsz + c8]);
        }
        CP_COMMIT();
    }

    float oacc[8][4];
#pragma unroll
    for (int df = 0; df < 8; ++df)
#pragma unroll
        for (int r = 0; r < 4; ++r) oacc[df][r] = 0.0f;
    float mrun[2] = {-INFINITY, -INFINITY};
    float lrun[2] = {0.0f, 0.0f};

    const int r0 = w * 16 + g;

    for (int kt = 0; kt < Ssz; kt += 64) {
        __syncthreads();   // prior tile fully consumed
        // ---- K tile via cp.async ----
        for (int i = tid; i < 64 * 8; i += 256) {
            int row = i >> 3, c8 = (i & 7) * 8;
            CP_ASYNC16(sbase + Kh_off + (uint32_t)(row * ASTR + c8) * 2,
                       &kph[(size_t)(kt + row) * Hsz + c8]);
            CP_ASYNC16(sbase + Kl_off + (uint32_t)(row * ASTR + c8) * 2,
                       &kpl[(size_t)(kt + row) * Hsz + c8]);
        }
        CP_COMMIT();
        // ---- V tile: uint4 LDG + transposed STS (bf16, no cvt) ----
        for (int i = tid; i < 64 * 8; i += 256) {
            int row = i >> 3, c8 = (i & 7) * 8;
            uint4 hv = *(const uint4*)&vph[(size_t)(kt + row) * Hsz + c8];
            uint4 lv = *(const uint4*)&vpl[(size_t)(kt + row) * Hsz + c8];
            const __nv_bfloat16* hp = (const __nv_bfloat16*)&hv;
            const __nv_bfloat16* lp = (const __nv_bfloat16*)&lv;
#pragma unroll
            for (int j = 0; j < 8; ++j) {
                Vth[(c8 + j) * ASTR + row] = hp[j];
                Vtl[(c8 + j) * ASTR + row] = lp[j];
            }
        }
        CP_WAIT0();
        __syncthreads();

        // ---- S = Q K^T (split, fp32 accum) ----
        float sacc[8][4];
#pragma unroll
        for (int nf = 0; nf < 8; ++nf)
#pragma unroll
            for (int r = 0; r < 4; ++r) sacc[nf][r] = 0.0f;

#pragma unroll
        for (int kc = 0; kc < 4; ++kc) {
            const int ko = kc * 16 + 2 * t;
            uint32_t ah[4], al[4];
            ah[0] = *(const uint32_t*)&Qh[r0 * ASTR + ko];
            ah[1] = *(const uint32_t*)&Qh[(r0 + 8) * ASTR + ko];
            ah[2] = *(const uint32_t*)&Qh[r0 * ASTR + ko + 8];
            ah[3] = *(const uint32_t*)&Qh[(r0 + 8) * ASTR + ko + 8];
            al[0] = *(const uint32_t*)&Ql[r0 * ASTR + ko];
            al[1] = *(const uint32_t*)&Ql[(r0 + 8) * ASTR + ko];
            al[2] = *(const uint32_t*)&Ql[r0 * ASTR + ko + 8];
            al[3] = *(const uint32_t*)&Ql[(r0 + 8) * ASTR + ko + 8];
#pragma unroll
            for (int nf = 0; nf < 8; ++nf) {
                int n = nf * 8 + g;
                uint32_t bh2[2], bl2[2];
                bh2[0] = *(const uint32_t*)&Kh[n * ASTR + ko];
                bh2[1] = *(const uint32_t*)&Kh[n * ASTR + ko + 8];
                bl2[0] = *(const uint32_t*)&Kl[n * ASTR + ko];
                bl2[1] = *(const uint32_t*)&Kl[n * ASTR + ko + 8];
                MMA16816(sacc[nf], ah, bh2);
                MMA16816(sacc[nf], ah, bl2);
                MMA16816(sacc[nf], al, bh2);
            }
        }

        // ---- positional bias + online softmax ----
        float rmax[2] = {-INFINITY, -INFINITY};
#pragma unroll
        for (int nf = 0; nf < 8; ++nf)
#pragma unroll
            for (int e = 0; e < 4; ++e) {
                int rr = e >> 1, cc = e & 1;
                float qi = (float)(qbase + r0 + rr * 8);
                float kj = (float)(kt + nf * 8 + 2 * t + cc);
                float dist = fabsf(qi - kj);
                float pb = __expf(-0.1f * fminf(dist, 5.0f));
                float s = (sacc[nf][e] + pb) * 0.125f - 0.1f * dist;
                sacc[nf][e] = s;
                rmax[rr] = fmaxf(rmax[rr], s);
            }
#pragma unroll
        for (int rr = 0; rr < 2; ++rr) {
            rmax[rr] = fmaxf(rmax[rr], __shfl_xor_sync(0xffffffffu, rmax[rr], 1));
            rmax[rr] = fmaxf(rmax[rr], __shfl_xor_sync(0xffffffffu, rmax[rr], 2));
        }
        float mnew[2], scale[2], lsum[2] = {0.0f, 0.0f};
#pragma unroll
        for (int rr = 0; rr < 2; ++rr) {
            mnew[rr]  = fmaxf(mrun[rr], rmax[rr]);
            scale[rr] = __expf(mrun[rr] - mnew[rr]);
            mrun[rr]  = mnew[rr];
        }
#pragma unroll
        for (int nf = 0; nf < 8; ++nf)
#pragma unroll
            for (int e = 0; e < 4; ++e) {
                int rr = e >> 1;
                float p = __expf(sacc[nf][e] - mnew[rr]);
                sacc[nf][e] = p;
                lsum[rr] += p;
            }
#pragma unroll
        for (int rr = 0; rr < 2; ++rr) {
            lsum[rr] += __shfl_xor_sync(0xffffffffu, lsum[rr], 1);
            lsum[rr] += __shfl_xor_sync(0xffffffffu, lsum[rr], 2);
            lrun[rr] = lrun[rr] * scale[rr] + lsum[rr];
        }
#pragma unroll
        for (int df = 0; df < 8; ++df) {
            oacc[df][0] *= scale[0];
            oacc[df][1] *= scale[0];
            oacc[df][2] *= scale[1];
            oacc[df][3] *= scale[1];
        }

        // ---- PV (split P x split V^T) ----
#pragma unroll
        for (int c = 0; c < 4; ++c) {
            uint32_t ph[4], pl[4];
            float p00 = sacc[2 * c][0],     p01 = sacc[2 * c][1];
            float p10 = sacc[2 * c][2],     p11 = sacc[2 * c][3];
            float p20 = sacc[2 * c + 1][0], p21 = sacc[2 * c + 1][1];
            float p30 = sacc[2 * c + 1][2], p31 = sacc[2 * c + 1][3];
            split_pair(p00, p01, ph[0], pl[0]);
            split_pair(p10, p11, ph[1], pl[1]);
            split_pair(p20, p21, ph[2], pl[2]);
            split_pair(p30, p31, ph[3], pl[3]);
            const int kk = c * 16 + 2 * t;
#pragma unroll
            for (int df = 0; df < 8; ++df) {
                int n = df * 8 + g;
                uint32_t bh2[2], bl2[2];
                bh2[0] = *(const uint32_t*)&Vth[n * ASTR + kk];
                bh2[1] = *(const uint32_t*)&Vth[n * ASTR + kk + 8];
                bl2[0] = *(const uint32_t*)&Vtl[n * ASTR + kk];
                bl2[1] = *(const uint32_t*)&Vtl[n * ASTR + kk + 8];
                MMA16816(oacc[df], ph, bh2);
                MMA16816(oacc[df], ph, bl2);
                MMA16816(oacc[df], pl, bh2);
            }
        }
    }

    // ---- epilogue: ctx split bf16 ----
    float inv0 = 1.0f / lrun[0], inv1 = 1.0f / lrun[1];
    size_t base0 = ((size_t)b * Ssz + qbase + r0) * Hsz + h * Dd;
#pragma unroll
    for (int df = 0; df < 8; ++df) {
        int col = df * 8 + 2 * t;
        uint32_t h0, l0, h1, l1;
        split_pair(oacc[df][0] * inv0, oacc[df][1] * inv0, h0, l0);
        split_pair(oacc[df][2] * inv1, oacc[df][3] * inv1, h1, l1);
        *(uint32_t*)&ch[base0 + col]            = h0;
        *(uint32_t*)&cl[base0 + col]            = l0;
        *(uint32_t*)&ch[base0 + 8 * Hsz + col]  = h1;
        *(uint32_t*)&cl[base0 + 8 * Hsz + col]  = l1;
    }
}

// ---------------- fused LayerNorm + classifier ----------------------------
__global__ __launch_bounds__(256)
void lnorm_cls(const float* __restrict__ y, const float* __restrict__ g,
               const float* __restrict__ bt, const float* __restrict__ Ws,
               const float* __restrict__ bs, float* __restrict__ span)
{
    const int row = blockIdx.x;
    const int tid = threadIdx.x;
    const float* yr = y + (size_t)row * Hsz;

    __shared__ float sy[Hsz];
    __shared__ float r1[256], r2[256];

    float s1 = 0.0f, s2 = 0.0f;
    for (int i = tid; i < Hsz; i += 256) {
        float v = yr[i];
        sy[i] = v;
        s1 += v;
        s2 += v * v;
    }
    r1[tid] = s1; r2[tid] = s2;
    __syncthreads();
    for (int off = 128; off > 0; off >>= 1) {
        if (tid < off) { r1[tid] += r1[tid + off]; r2[tid] += r2[tid + off]; }
        __syncthreads();
    }
    float mu  = r1[0] * (1.0f / Hsz);
    float var = r2[0] * (1.0f / Hsz) - mu * mu;
    float inv = rsqrtf(var + 1e-5f);

    float acc[Ln];
#pragma unroll
    for (int l = 0; l < Ln; l++) acc[l] = 0.0f;
    for (int kk = tid; kk < Hsz; kk += 256) {
        float x = (sy[kk] - mu) * inv * g[kk] + bt[kk];
        const float* wr = Ws + kk * Ln;
#pragma unroll
        for (int l = 0; l < Ln; l++) acc[l] = fmaf(x, wr[l], acc[l]);
    }
#pragma unroll
    for (int l = 0; l < Ln; l++)
#pragma unroll
        for (int off = 16; off >= 1; off >>= 1)
            acc[l] += __shfl_xor_sync(0xffffffffu, acc[l], off);

    __shared__ float red[8][Ln];
    int warp = tid >> 5, lane = tid & 31;
    if (lane == 0)
#pragma unroll
        for (int l = 0; l < Ln; l++) red[warp][l] = acc[l];
    __syncthreads();
    if (tid < Ln) {
        float s = bs[tid];
#pragma unroll
        for (int w = 0; w < 8; w++) s += red[w][tid];
        span[(size_t)row * Ln + tid] = s;
    }
}

// ---------------- entity-bias finalize ------------------------------------
__global__ __launch_bounds__(256)
void finalize(const float* __restrict__ span, const float* __restrict__ eb,
              float* __restrict__ out)
{
    int idx = blockIdx.x * 256 + threadIdx.x;
    if (idx >= ROWS) return;
    int s = idx & (Ssz - 1);

    float vals[Ln];
#pragma unroll
    for (int l = 0; l < Ln; l++) vals[l] = span[idx * Ln + l];

    if (s > 0) {
        const float* pr = span + (idx - 1) * Ln;
        float best = pr[0];
        int bi = 0;
#pragma unroll
        for (int l = 1; l < Ln; l++)
            if (pr[l] > best) { best = pr[l]; bi = l; }
        if (bi == 1) vals[2] += 2.0f * eb[2];
    }
#pragma unroll
    for (int l = 0; l < Ln; l++) out[idx * Ln + l] = vals[l];
}

// ---------------- launch ---------------------------------------------------
extern "C" void kernel_launch(void* const* d_in, const int* in_sizes, int n_in,
                              void* d_out, int out_size)
{
    const float* X    = (const float*)d_in[0];
    const float* Wq   = (const float*)d_in[1];
    const float* bq   = (const float*)d_in[2];
    const float* Wk   = (const float*)d_in[3];
    const float* bk   = (const float*)d_in[4];
    const float* Wv   = (const float*)d_in[5];
    const float* bv   = (const float*)d_in[6];
    const float* Wo   = (const float*)d_in[7];
    const float* bo   = (const float*)d_in[8];
    const float* ln_g = (const float*)d_in[9];
    const float* ln_b = (const float*)d_in[10];
    const float* Ws   = (const float*)d_in[11];
    const float* bs   = (const float*)d_in[12];
    const float* eb   = (const float*)d_in[13];
    float* out = (float*)d_out;

    float *y, *span;
    cudaGetSymbolAddress((void**)&y,    g_y);
    cudaGetSymbolAddress((void**)&span, g_span);

    __nv_bfloat16 *xh, *xl, *qh, *ql, *kh, *kl, *vh, *vl, *ch, *cl, *wth, *wtl;
    cudaGetSymbolAddress((void**)&xh,  g_xh);
    cudaGetSymbolAddress((void**)&xl,  g_xl);
    cudaGetSymbolAddress((void**)&qh,  g_qh);
    cudaGetSymbolAddress((void**)&ql,  g_ql);
    cudaGetSymbolAddress((void**)&kh,  g_kh);
    cudaGetSymbolAddress((void**)&kl,  g_kl);
    cudaGetSymbolAddress((void**)&vh,  g_vh);
    cudaGetSymbolAddress((void**)&vl,  g_vl);
    cudaGetSymbolAddress((void**)&ch,  g_ch);
    cudaGetSymbolAddress((void**)&cl,  g_cl);
    cudaGetSymbolAddress((void**)&wth, g_wth);
    cudaGetSymbolAddress((void**)&wtl, g_wtl);
    const size_t WSZ = (size_t)Hsz * Hsz;

    cudaFuncSetAttribute(attn_mma, cudaFuncAttributeMaxDynamicSharedMemorySize,
                         ATTN_MMA_SMEM);
    cudaFuncSetAttribute(gemm_mma<false, true>, cudaFuncAttributeMaxDynamicSharedMemorySize,
                         GMMA_SMEM);
    cudaFuncSetAttribute(gemm_mma<true, false>, cudaFuncAttributeMaxDynamicSharedMemorySize,
                         GMMA_SMEM);

    // --- operand prep ---
    const int n4 = ROWS * Hsz / 4;
    split_f32<<<(n4 + 255) / 256, 256>>>(X, xh, xl, n4);
    dim3 wb(32, 8), wg(32, 32);
    wsplit_t<<<wg, wb>>>(Wq, wth + 0 * WSZ, wtl + 0 * WSZ);
    wsplit_t<<<wg, wb>>>(Wk, wth + 1 * WSZ, wtl + 1 * WSZ);
    wsplit_t<<<wg, wb>>>(Wv, wth + 2 * WSZ, wtl + 2 * WSZ);
    wsplit_t<<<wg, wb>>>(Wo, wth + 3 * WSZ, wtl + 3 * WSZ);

    // --- projections: emit split-bf16 directly ---
    dim3 gg(Hsz / 128, ROWS / 128);   // (8, 32)
    gemm_mma<false, true><<<gg, 256, GMMA_SMEM>>>(xh, xl, wth + 0 * WSZ, wtl + 0 * WSZ,
                                                  bq, nullptr, nullptr, qh, ql);
    gemm_mma<false, true><<<gg, 256, GMMA_SMEM>>>(xh, xl, wth + 1 * WSZ, wtl + 1 * WSZ,
                                                  bk, nullptr, nullptr, kh, kl);
    gemm_mma<false, true><<<gg, 256, GMMA_SMEM>>>(xh, xl, wth + 2 * WSZ, wtl + 2 * WSZ,
                                                  bv, nullptr, nullptr, vh, vl);

    // --- attention (bf16-split in, bf16-split out) ---
    dim3 ga(Ssz / 128, Bc * NHn);     // (8, 64)
    attn_mma<<<ga, 256, ATTN_MMA_SMEM>>>(qh, ql, kh, kl, vh, vl, ch, cl);

    // --- output projection + residual (fp32 out) ---
    gemm_mma<true, false><<<gg, 256, GMMA_SMEM>>>(ch, cl, wth + 3 * WSZ, wtl + 3 * WSZ,
                                                  bo, X, y, nullptr, nullptr);

    lnorm_cls<<<ROWS, 256>>>(y, ln_g, ln_b, Ws, bs, span);
    finalize<<<(ROWS + 255) / 256, 256>>>(span, eb, out);
}

// round 15
// speedup vs baseline: 2.4055x; 1.0828x over previous
#include <cuda_runtime.h>
#include <cuda_bf16.h>
#include <math.h>
#include <stdint.h>

#define Bc   4
#define Ssz  1024
#define Hsz  1024
#define NHn  16
#define Dd   64
#define Ln   9
#define ROWS (Bc * Ssz)          // 4096

// ---------------- scratch (device globals, no allocation) ----------------
__device__ float g_y  [ROWS * Hsz];
__device__ float g_span[ROWS * Ln];

// bf16 split operands
__device__ __nv_bfloat16 g_xh[ROWS * Hsz], g_xl[ROWS * Hsz];       // X hi/lo
__device__ __nv_bfloat16 g_qh[ROWS * Hsz], g_ql[ROWS * Hsz];
__device__ __nv_bfloat16 g_kh[ROWS * Hsz], g_kl[ROWS * Hsz];
__device__ __nv_bfloat16 g_vh[ROWS * Hsz], g_vl[ROWS * Hsz];
__device__ __nv_bfloat16 g_ch[ROWS * Hsz], g_cl[ROWS * Hsz];       // ctx hi/lo
__device__ __nv_bfloat16 g_wth[4][Hsz * Hsz], g_wtl[4][Hsz * Hsz]; // W^T hi/lo

// ============================ helpers ====================================
__device__ __forceinline__ uint32_t smem_u32(const void* p) {
    uint32_t a;
    asm("{ .reg .u64 t; cvta.to.shared.u64 t, %1; cvt.u32.u64 %0, t; }"
        : "=r"(a) : "l"(p));
    return a;
}
#define CP_ASYNC16(sm, gm) \
    asm volatile("cp.async.cg.shared.global [%0], [%1], 16;" :: "r"(sm), "l"(gm))
#define CP_COMMIT() asm volatile("cp.async.commit_group;" ::: "memory")
#define CP_WAIT0()  asm volatile("cp.async.wait_group 0;" ::: "memory")
#define CP_WAIT1()  asm volatile("cp.async.wait_group 1;" ::: "memory")

// D(16x8,f32) += A(16x16,bf16 row) * B(16x8,bf16 col)
#define MMA16816(cc, aa, bb) \
    asm volatile("mma.sync.aligned.m16n8k16.row.col.f32.bf16.bf16.f32 " \
        "{%0,%1,%2,%3}, {%4,%5,%6,%7}, {%8,%9}, {%0,%1,%2,%3};" \
        : "+f"((cc)[0]), "+f"((cc)[1]), "+f"((cc)[2]), "+f"((cc)[3]) \
        : "r"((aa)[0]), "r"((aa)[1]), "r"((aa)[2]), "r"((aa)[3]), \
          "r"((bb)[0]), "r"((bb)[1]))

__device__ __forceinline__ uint32_t pack_bf16x2(float a, float b) {
    __nv_bfloat162 h = __floats2bfloat162_rn(a, b);
    return *(uint32_t*)&h;
}
// split pair (a,b) -> hi uint32 / lo uint32
__device__ __forceinline__ void split_pair(float a, float b, uint32_t& hi, uint32_t& lo) {
    __nv_bfloat16 ha = __float2bfloat16(a), hb = __float2bfloat16(b);
    __nv_bfloat16 la = __float2bfloat16(a - __bfloat162float(ha));
    __nv_bfloat16 lb = __float2bfloat16(b - __bfloat162float(hb));
    __nv_bfloat162 hh(ha, hb), ll(la, lb);
    hi = *(uint32_t*)&hh;
    lo = *(uint32_t*)&ll;
}

// ================= split / transpose prep kernels ========================
__global__ __launch_bounds__(256)
void split_f32(const float* __restrict__ src, __nv_bfloat16* __restrict__ hi,
               __nv_bfloat16* __restrict__ lo, int n4)
{
    int i = blockIdx.x * 256 + threadIdx.x;
    if (i >= n4) return;
    float4 x = ((const float4*)src)[i];
    uint32_t h0, l0, h1, l1;
    split_pair(x.x, x.y, h0, l0);
    split_pair(x.z, x.w, h1, l1);
    ((uint32_t*)hi)[2 * i]     = h0;
    ((uint32_t*)hi)[2 * i + 1] = h1;
    ((uint32_t*)lo)[2 * i]     = l0;
    ((uint32_t*)lo)[2 * i + 1] = l1;
}

// W[k][n] (row-major KxN) -> Wt[n][k] bf16 hi/lo
__global__ __launch_bounds__(256)
void wsplit_t(const float* __restrict__ W, __nv_bfloat16* __restrict__ th,
              __nv_bfloat16* __restrict__ tl)
{
    __shared__ float t[32][33];
    int tx = threadIdx.x, ty = threadIdx.y;          // (32, 8)
    int n0 = blockIdx.x * 32, k0 = blockIdx.y * 32;
#pragma unroll
    for (int i = 0; i < 32; i += 8)
        t[ty + i][tx] = W[(size_t)(k0 + ty + i) * Hsz + n0 + tx];
    __syncthreads();
#pragma unroll
    for (int i = 0; i < 32; i += 8) {
        float v = t[tx][ty + i];
        __nv_bfloat16 h = __float2bfloat16(v);
        __nv_bfloat16 l = __float2bfloat16(v - __bfloat162float(h));
        size_t o = (size_t)(n0 + ty + i) * Hsz + k0 + tx;
        th[o] = h;
        tl[o] = l;
    }
}

// ================= mma.sync split-bf16 GEMM ==============================
// SPLIT=true:  write Ch/Cl split-bf16 (for q/k/v).  SPLIT=false: fp32 C (+R).
#define BKc   32
#define STRs  48
#define TILEE (128 * STRs)
#define SLAB4 (4 * TILEE)
#define GMMA_SMEM (2 * SLAB4 * 2)     // 98304 bytes

template <bool RESID, bool SPLIT>
__global__ __launch_bounds__(256, 2)
void gemm_mma(const __nv_bfloat16* __restrict__ Ah, const __nv_bfloat16* __restrict__ Al,
              const __nv_bfloat16* __restrict__ Bh, const __nv_bfloat16* __restrict__ Bl,
              const float* __restrict__ bias, const float* __restrict__ R,
              float* __restrict__ C,
              __nv_bfloat16* __restrict__ Ch, __nv_bfloat16* __restrict__ Cl)
{
    extern __shared__ __nv_bfloat16 sb[];
    const uint32_t sbase = smem_u32(sb);

    const int tid  = threadIdx.x;
    const int lane = tid & 31;
    const int wid  = tid >> 5;
    const int wm   = wid & 1;
    const int wn   = wid >> 1;
    const int g    = lane >> 2;
    const int t    = lane & 3;
    const int bn   = blockIdx.x * 128;
    const int bm   = blockIdx.y * 128;

    const int lrow = tid >> 2;
    const int lc4  = tid & 3;
    const __nv_bfloat16* gsrc[4] = {Ah, Al, Bh, Bl};
    const int gbase[4] = {bm, bm, bn, bn};

    float acc[4][4][4];
#pragma unroll
    for (int i = 0; i < 4; i++)
#pragma unroll
        for (int j = 0; j < 4; j++)
#pragma unroll
            for (int r = 0; r < 4; r++) acc[i][j][r] = 0.0f;

    auto issue = [&](int c, int b) {
#pragma unroll
        for (int s = 0; s < 4; ++s)
#pragma unroll
            for (int i = 0; i < 2; ++i) {
                int row = lrow + i * 64;
                const void* gp = &gsrc[s][(size_t)(gbase[s] + row) * Hsz + c * BKc + lc4 * 8];
                uint32_t sp = sbase + (uint32_t)(b * SLAB4 + s * TILEE + row * STRs + lc4 * 8) * 2;
                CP_ASYNC16(sp, gp);
            }
    };

    issue(0, 0);
    CP_COMMIT();

    for (int c = 0; c < Hsz / BKc; ++c) {
        if (c + 1 < Hsz / BKc) { issue(c + 1, (c + 1) & 1); CP_COMMIT(); CP_WAIT1(); }
        else                   { CP_WAIT0(); }
        __syncthreads();

        const __nv_bfloat16* As_h = sb + (c & 1) * SLAB4;
        const __nv_bfloat16* As_l = As_h + TILEE;
        const __nv_bfloat16* Bs_h = As_l + TILEE;
        const __nv_bfloat16* Bs_l = Bs_h + TILEE;

#pragma unroll
        for (int k0 = 0; k0 < BKc; k0 += 16) {
            uint32_t bh[4][2], bl[4][2];
#pragma unroll
            for (int nt = 0; nt < 4; ++nt) {
                int n = wn * 32 + nt * 8 + g;
                bh[nt][0] = *(const uint32_t*)&Bs_h[n * STRs + k0 + 2 * t];
                bh[nt][1] = *(const uint32_t*)&Bs_h[n * STRs + k0 + 2 * t + 8];
                bl[nt][0] = *(const uint32_t*)&Bs_l[n * STRs + k0 + 2 * t];
                bl[nt][1] = *(const uint32_t*)&Bs_l[n * STRs + k0 + 2 * t + 8];
            }
            uint32_t af[4][4];
#pragma unroll
            for (int mt = 0; mt < 4; ++mt) {
                int row = wm * 64 + mt * 16 + g;
                af[mt][0] = *(const uint32_t*)&As_h[row * STRs + k0 + 2 * t];
                af[mt][1] = *(const uint32_t*)&As_h[(row + 8) * STRs + k0 + 2 * t];
                af[mt][2] = *(const uint32_t*)&As_h[row * STRs + k0 + 2 * t + 8];
                af[mt][3] = *(const uint32_t*)&As_h[(row + 8) * STRs + k0 + 2 * t + 8];
            }
#pragma unroll
            for (int mt = 0; mt < 4; ++mt)
#pragma unroll
                for (int nt = 0; nt < 4; ++nt) {
                    MMA16816(acc[mt][nt], af[mt], bh[nt]);
                    MMA16816(acc[mt][nt], af[mt], bl[nt]);
                }
#pragma unroll
            for (int mt = 0; mt < 4; ++mt) {
                int row = wm * 64 + mt * 16 + g;
                af[mt][0] = *(const uint32_t*)&As_l[row * STRs + k0 + 2 * t];
                af[mt][1] = *(const uint32_t*)&As_l[(row + 8) * STRs + k0 + 2 * t];
                af[mt][2] = *(const uint32_t*)&As_l[row * STRs + k0 + 2 * t + 8];
                af[mt][3] = *(const uint32_t*)&As_l[(row + 8) * STRs + k0 + 2 * t + 8];
            }
#pragma unroll
            for (int mt = 0; mt < 4; ++mt)
#pragma unroll
                for (int nt = 0; nt < 4; ++nt)
                    MMA16816(acc[mt][nt], af[mt], bh[nt]);
        }
        __syncthreads();
    }

#pragma unroll
    for (int mt = 0; mt < 4; ++mt) {
        int row = bm + wm * 64 + mt * 16 + g;
#pragma unroll
        for (int nt = 0; nt < 4; ++nt) {
            int col = bn + wn * 32 + nt * 8 + 2 * t;
            float b0 = bias[col], b1 = bias[col + 1];
            float v0 = acc[mt][nt][0] + b0;
            float v1 = acc[mt][nt][1] + b1;
            float v2 = acc[mt][nt][2] + b0;
            float v3 = acc[mt][nt][3] + b1;
            if (SPLIT) {
                uint32_t h0, l0, h1, l1;
                split_pair(v0, v1, h0, l0);
                split_pair(v2, v3, h1, l1);
                *(uint32_t*)&Ch[(size_t)row * Hsz + col]       = h0;
                *(uint32_t*)&Cl[(size_t)row * Hsz + col]       = l0;
                *(uint32_t*)&Ch[(size_t)(row + 8) * Hsz + col] = h1;
                *(uint32_t*)&Cl[(size_t)(row + 8) * Hsz + col] = l1;
            } else {
                if (RESID) {
                    const float* r0 = &R[(size_t)row * Hsz + col];
                    const float* r8 = &R[(size_t)(row + 8) * Hsz + col];
                    v0 += r0[0]; v1 += r0[1];
                    v2 += r8[0]; v3 += r8[1];
                }
                *(float2*)&C[(size_t)row * Hsz + col]       = make_float2(v0, v1);
                *(float2*)&C[(size_t)(row + 8) * Hsz + col] = make_float2(v2, v3);
            }
        }
    }
}

// ================= mma.sync flash attention (bf16-split inputs) ==========
// Double-buffered K (cp.async) + V (LDG->regs->swizzled STS transpose).
// V swizzle: element (d,key) at d*ASTR + (key ^ (((d>>3)&7)<<3))  — makes both
// the transposed stores and the B-fragment reads bank-conflict-free.
// One __syncthreads per key tile.
#define ASTR 72
#define AQ_ELE (128 * ASTR)
#define AK_ELE (64 * ASTR)
#define ATTN_MMA_SMEM ((2 * AQ_ELE + 8 * AK_ELE) * 2)   // 110592 bytes

__global__ __launch_bounds__(256, 2)
void attn_mma(const __nv_bfloat16* __restrict__ qh, const __nv_bfloat16* __restrict__ ql,
              const __nv_bfloat16* __restrict__ kh, const __nv_bfloat16* __restrict__ kl,
              const __nv_bfloat16* __restrict__ vh, const __nv_bfloat16* __restrict__ vl,
              __nv_bfloat16* __restrict__ ch, __nv_bfloat16* __restrict__ cl)
{
    extern __shared__ __nv_bfloat16 as[];
    __nv_bfloat16* Qh = as;
    __nv_bfloat16* Ql = as + AQ_ELE;
    const uint32_t sbase = smem_u32(as);
    const uint32_t KBASE = 2 * AQ_ELE;            // elements
    const uint32_t VBASE = 2 * AQ_ELE + 4 * AK_ELE;

    const int bh = blockIdx.y;
    const int b  = bh >> 4;
    const int h  = bh & 15;
    const int qbase = blockIdx.x * 128;

    const int tid  = threadIdx.x;
    const int lane = tid & 31;
    const int w    = tid >> 5;
    const int g    = lane >> 2;
    const int t    = lane & 3;

    const size_t hb = ((size_t)b * Ssz) * Hsz + h * Dd;
    const __nv_bfloat16* qph = qh + hb;
    const __nv_bfloat16* qpl = ql + hb;
    const __nv_bfloat16* kph = kh + hb;
    const __nv_bfloat16* kpl = kl + hb;
    const __nv_bfloat16* vph = vh + hb;
    const __nv_bfloat16* vpl = vl + hb;

    // per-thread staging coords (2 items of 8 bf16 per tile per array)
    const int srow0 = tid >> 3;            // V/K item 0 row for K uses below
    const int sc8   = (tid & 7) * 8;

    // ---- stage Q (cp.async) + K tile 0 (cp.async), one commit ----
    for (int i = tid; i < 128 * 8; i += 256) {
        int row = i >> 3, c8 = (i & 7) * 8;
        CP_ASYNC16(sbase + (uint32_t)(row * ASTR + c8) * 2,
                   &qph[(size_t)(qbase + row) * Hsz + c8]);
        CP_ASYNC16(sbase + (uint32_t)(AQ_ELE + row * ASTR + c8) * 2,
                   &qpl[(size_t)(qbase + row) * Hsz + c8]);
    }
#pragma unroll
    for (int it = 0; it < 2; ++it) {
        int row = srow0 + it * 32;
        CP_ASYNC16(sbase + (uint32_t)(KBASE + row * ASTR + sc8) * 2,
                   &kph[(size_t)row * Hsz + sc8]);
        CP_ASYNC16(sbase + (uint32_t)(KBASE + AK_ELE + row * ASTR + sc8) * 2,
                   &kpl[(size_t)row * Hsz + sc8]);
    }
    CP_COMMIT();

    // ---- prefetch V tile 0 into registers ----
    uint4 vrh[2], vrl[2];
#pragma unroll
    for (int it = 0; it < 2; ++it) {
        int row = srow0 + it * 32;
        vrh[it] = *(const uint4*)&vph[(size_t)row * Hsz + sc8];
        vrl[it] = *(const uint4*)&vpl[(size_t)row * Hsz + sc8];
    }

    float oacc[8][4];
#pragma unroll
    for (int df = 0; df < 8; ++df)
#pragma unroll
        for (int r = 0; r < 4; ++r) oacc[df][r] = 0.0f;
    float mrun[2] = {-INFINITY, -INFINITY};
    float lrun[2] = {0.0f, 0.0f};

    const int r0 = w * 16 + g;

    for (int ti = 0; ti < Ssz / 64; ++ti) {
        const int kt  = ti * 64;
        const int buf = ti & 1;
        __nv_bfloat16* KhB = as + KBASE + buf * 2 * AK_ELE;
        __nv_bfloat16* KlB = KhB + AK_ELE;
        __nv_bfloat16* VthB = as + VBASE + buf * 2 * AK_ELE;
        __nv_bfloat16* VtlB = VthB + AK_ELE;

        // ---- swizzled transposed STS of prefetched V (buf ti&1) ----
        // safe pre-sync: tile ti-1 readers use buf (ti-1)&1 != buf
        {
            const __nv_bfloat16* hp0 = (const __nv_bfloat16*)&vrh[0];
            const __nv_bfloat16* lp0 = (const __nv_bfloat16*)&vrl[0];
            const __nv_bfloat16* hp1 = (const __nv_bfloat16*)&vrh[1];
            const __nv_bfloat16* lp1 = (const __nv_bfloat16*)&vrl[1];
#pragma unroll
            for (int j = 0; j < 8; ++j) {
                int d = sc8 + j;
                int sw = ((d >> 3) & 7) << 3;
                int row0 = srow0, row1 = srow0 + 32;
                VthB[d * ASTR + (row0 ^ sw)] = hp0[j];
                VtlB[d * ASTR + (row0 ^ sw)] = lp0[j];
                VthB[d * ASTR + (row1 ^ sw)] = hp1[j];
                VtlB[d * ASTR + (row1 ^ sw)] = lp1[j];
            }
        }

        CP_WAIT0();            // K(ti) (and Q on ti=0) arrived
        __syncthreads();       // all smem (Q, K(ti), V(ti)) visible; ti-1 retired

        // ---- prefetch next tile: K cp.async + V LDG (overlaps compute) ----
        if (ti + 1 < Ssz / 64) {
            const int nbuf = (ti + 1) & 1;
            const int nkt  = kt + 64;
#pragma unroll
            for (int it = 0; it < 2; ++it) {
                int row = srow0 + it * 32;
                CP_ASYNC16(sbase + (uint32_t)(KBASE + nbuf * 2 * AK_ELE + row * ASTR + sc8) * 2,
                           &kph[(size_t)(nkt + row) * Hsz + sc8]);
                CP_ASYNC16(sbase + (uint32_t)(KBASE + nbuf * 2 * AK_ELE + AK_ELE + row * ASTR + sc8) * 2,
                           &kpl[(size_t)(nkt + row) * Hsz + sc8]);
            }
            CP_COMMIT();
#pragma unroll
            for (int it = 0; it < 2; ++it) {
                int row = srow0 + it * 32;
                vrh[it] = *(const uint4*)&vph[(size_t)(nkt + row) * Hsz + sc8];
                vrl[it] = *(const uint4*)&vpl[(size_t)(nkt + row) * Hsz + sc8];
            }
        }

        // ---- S = Q K^T (split, fp32 accum) ----
        float sacc[8][4];
#pragma unroll
        for (int nf = 0; nf < 8; ++nf)
#pragma unroll
            for (int r = 0; r < 4; ++r) sacc[nf][r] = 0.0f;

#pragma unroll
        for (int kc = 0; kc < 4; ++kc) {
            const int ko = kc * 16 + 2 * t;
            uint32_t ah[4], al[4];
            ah[0] = *(const uint32_t*)&Qh[r0 * ASTR + ko];
            ah[1] = *(const uint32_t*)&Qh[(r0 + 8) * ASTR + ko];
            ah[2] = *(const uint32_t*)&Qh[r0 * ASTR + ko + 8];
            ah[3] = *(const uint32_t*)&Qh[(r0 + 8) * ASTR + ko + 8];
            al[0] = *(const uint32_t*)&Ql[r0 * ASTR + ko];
            al[1] = *(const uint32_t*)&Ql[(r0 + 8) * ASTR + ko];
            al[2] = *(const uint32_t*)&Ql[r0 * ASTR + ko + 8];
            al[3] = *(const uint32_t*)&Ql[(r0 + 8) * ASTR + ko + 8];
#pragma unroll
            for (int nf = 0; nf < 8; ++nf) {
                int n = nf * 8 + g;
                uint32_t bh2[2], bl2[2];
                bh2[0] = *(const uint32_t*)&KhB[n * ASTR + ko];
                bh2[1] = *(const uint32_t*)&KhB[n * ASTR + ko + 8];
                bl2[0] = *(const uint32_t*)&KlB[n * ASTR + ko];
                bl2[1] = *(const uint32_t*)&KlB[n * ASTR + ko + 8];
                MMA16816(sacc[nf], ah, bh2);
                MMA16816(sacc[nf], ah, bl2);
                MMA16816(sacc[nf], al, bh2);
            }
        }

        // ---- positional bias + online softmax ----
        float rmax[2] = {-INFINITY, -INFINITY};
#pragma unroll
        for (int nf = 0; nf < 8; ++nf)
#pragma unroll
            for (int e = 0; e < 4; ++e) {
                int rr = e >> 1, cc = e & 1;
                float qi = (float)(qbase + r0 + rr * 8);
                float kj = (float)(kt + nf * 8 + 2 * t + cc);
                float dist = fabsf(qi - kj);
                float pb = __expf(-0.1f * fminf(dist, 5.0f));
                float s = (sacc[nf][e] + pb) * 0.125f - 0.1f * dist;
                sacc[nf][e] = s;
                rmax[rr] = fmaxf(rmax[rr], s);
            }
#pragma unroll
        for (int rr = 0; rr < 2; ++rr) {
            rmax[rr] = fmaxf(rmax[rr], __shfl_xor_sync(0xffffffffu, rmax[rr], 1));
            rmax[rr] = fmaxf(rmax[rr], __shfl_xor_sync(0xffffffffu, rmax[rr], 2));
        }
        float mnew[2], scale[2], lsum[2] = {0.0f, 0.0f};
#pragma unroll
        for (int rr = 0; rr < 2; ++rr) {
            mnew[rr]  = fmaxf(mrun[rr], rmax[rr]);
            scale[rr] = __expf(mrun[rr] - mnew[rr]);
            mrun[rr]  = mnew[rr];
        }
#pragma unroll
        for (int nf = 0; nf < 8; ++nf)
#pragma unroll
            for (int e = 0; e < 4; ++e) {
                int rr = e >> 1;
                float p = __expf(sacc[nf][e] - mnew[rr]);
                sacc[nf][e] = p;
                lsum[rr] += p;
            }
#pragma unroll
        for (int rr = 0; rr < 2; ++rr) {
            lsum[rr] += __shfl_xor_sync(0xffffffffu, lsum[rr], 1);
            lsum[rr] += __shfl_xor_sync(0xffffffffu, lsum[rr], 2);
            lrun[rr] = lrun[rr] * scale[rr] + lsum[rr];
        }
#pragma unroll
        for (int df = 0; df < 8; ++df) {
            oacc[df][0] *= scale[0];
            oacc[df][1] *= scale[0];
            oacc[df][2] *= scale[1];
            oacc[df][3] *= scale[1];
        }

        // ---- PV (split P x swizzled V^T) ----
#pragma unroll
        for (int c = 0; c < 4; ++c) {
            uint32_t ph[4], pl[4];
            float p00 = sacc[2 * c][0],     p01 = sacc[2 * c][1];
            float p10 = sacc[2 * c][2],     p11 = sacc[2 * c][3];
            float p20 = sacc[2 * c + 1][0], p21 = sacc[2 * c + 1][1];
            float p30 = sacc[2 * c + 1][2], p31 = sacc[2 * c + 1][3];
            split_pair(p00, p01, ph[0], pl[0]);
            split_pair(p10, p11, ph[1], pl[1]);
            split_pair(p20, p21, ph[2], pl[2]);
            split_pair(p30, p31, ph[3], pl[3]);
            const int kk = c * 16 + 2 * t;
#pragma unroll
            for (int df = 0; df < 8; ++df) {
                int n = df * 8 + g;
                int sw = (df & 7) << 3;
                uint32_t a0 = (uint32_t)(n * ASTR) + (uint32_t)(kk ^ sw);
                uint32_t a1 = (uint32_t)(n * ASTR) + (uint32_t)((kk + 8) ^ sw);
                uint32_t bh2[2], bl2[2];
                bh2[0] = *(const uint32_t*)&VthB[a0];
                bh2[1] = *(const uint32_t*)&VthB[a1];
                bl2[0] = *(const uint32_t*)&VtlB[a0];
                bl2[1] = *(const uint32_t*)&VtlB[a1];
                MMA16816(oacc[df], ph, bh2);
                MMA16816(oacc[df], ph, bl2);
                MMA16816(oacc[df], pl, bh2);
            }
        }
    }

    // ---- epilogue: ctx split bf16 ----
    float inv0 = 1.0f / lrun[0], inv1 = 1.0f / lrun[1];
    size_t base0 = ((size_t)b * Ssz + qbase + r0) * Hsz + h * Dd;
#pragma unroll
    for (int df = 0; df < 8; ++df) {
        int col = df * 8 + 2 * t;
        uint32_t h0, l0, h1, l1;
        split_pair(oacc[df][0] * inv0, oacc[df][1] * inv0, h0, l0);
        split_pair(oacc[df][2] * inv1, oacc[df][3] * inv1, h1, l1);
        *(uint32_t*)&ch[base0 + col]            = h0;
        *(uint32_t*)&cl[base0 + col]            = l0;
        *(uint32_t*)&ch[base0 + 8 * Hsz + col]  = h1;
        *(uint32_t*)&cl[base0 + 8 * Hsz + col]  = l1;
    }
}

// ---------------- fused LayerNorm + classifier ----------------------------
__global__ __launch_bounds__(256)
void lnorm_cls(const float* __restrict__ y, const float* __restrict__ g,
               const float* __restrict__ bt, const float* __restrict__ Ws,
               const float* __restrict__ bs, float* __restrict__ span)
{
    const int row = blockIdx.x;
    const int tid = threadIdx.x;
    const float* yr = y + (size_t)row * Hsz;

    __shared__ float sy[Hsz];
    __shared__ float r1[256], r2[256];

    float s1 = 0.0f, s2 = 0.0f;
    for (int i = tid; i < Hsz; i += 256) {
        float v = yr[i];
        sy[i] = v;
        s1 += v;
        s2 += v * v;
    }
    r1[tid] = s1; r2[tid] = s2;
    __syncthreads();
    for (int off = 128; off > 0; off >>= 1) {
        if (tid < off) { r1[tid] += r1[tid + off]; r2[tid] += r2[tid + off]; }
        __syncthreads();
    }
    float mu  = r1[0] * (1.0f / Hsz);
    float var = r2[0] * (1.0f / Hsz) - mu * mu;
    float inv = rsqrtf(var + 1e-5f);

    float acc[Ln];
#pragma unroll
    for (int l = 0; l < Ln; l++) acc[l] = 0.0f;
    for (int kk = tid; kk < Hsz; kk += 256) {
        float x = (sy[kk] - mu) * inv * g[kk] + bt[kk];
        const float* wr = Ws + kk * Ln;
#pragma unroll
        for (int l = 0; l < Ln; l++) acc[l] = fmaf(x, wr[l], acc[l]);
    }
#pragma unroll
    for (int l = 0; l < Ln; l++)
#pragma unroll
        for (int off = 16; off >= 1; off >>= 1)
            acc[l] += __shfl_xor_sync(0xffffffffu, acc[l], off);

    __shared__ float red[8][Ln];
    int warp = tid >> 5, lane = tid & 31;
    if (lane == 0)
#pragma unroll
        for (int l = 0; l < Ln; l++) red[warp][l] = acc[l];
    __syncthreads();
    if (tid < Ln) {
        float s = bs[tid];
#pragma unroll
        for (int w = 0; w < 8; w++) s += red[w][tid];
        span[(size_t)row * Ln + tid] = s;
    }
}

// ---------------- entity-bias finalize ------------------------------------
__global__ __launch_bounds__(256)
void finalize(const float* __restrict__ span, const float* __restrict__ eb,
              float* __restrict__ out)
{
    int idx = blockIdx.x * 256 + threadIdx.x;
    if (idx >= ROWS) return;
    int s = idx & (Ssz - 1);

    float vals[Ln];
#pragma unroll
    for (int l = 0; l < Ln; l++) vals[l] = span[idx * Ln + l];

    if (s > 0) {
        const float* pr = span + (idx - 1) * Ln;
        float best = pr[0];
        int bi = 0;
#pragma unroll
        for (int l = 1; l < Ln; l++)
            if (pr[l] > best) { best = pr[l]; bi = l; }
        if (bi == 1) vals[2] += 2.0f * eb[2];
    }
#pragma unroll
    for (int l = 0; l < Ln; l++) out[idx * Ln + l] = vals[l];
}

// ---------------- launch ---------------------------------------------------
extern "C" void kernel_launch(void* const* d_in, const int* in_sizes, int n_in,
                              void* d_out, int out_size)
{
    const float* X    = (const float*)d_in[0];
    const float* Wq   = (const float*)d_in[1];
    const float* bq   = (const float*)d_in[2];
    const float* Wk   = (const float*)d_in[3];
    const float* bk   = (const float*)d_in[4];
    const float* Wv   = (const float*)d_in[5];
    const float* bv   = (const float*)d_in[6];
    const float* Wo   = (const float*)d_in[7];
    const float* bo   = (const float*)d_in[8];
    const float* ln_g = (const float*)d_in[9];
    const float* ln_b = (const float*)d_in[10];
    const float* Ws   = (const float*)d_in[11];
    const float* bs   = (const float*)d_in[12];
    const float* eb   = (const float*)d_in[13];
    float* out = (float*)d_out;

    float *y, *span;
    cudaGetSymbolAddress((void**)&y,    g_y);
    cudaGetSymbolAddress((void**)&span, g_span);

    __nv_bfloat16 *xh, *xl, *qh, *ql, *kh, *kl, *vh, *vl, *ch, *cl, *wth, *wtl;
    cudaGetSymbolAddress((void**)&xh,  g_xh);
    cudaGetSymbolAddress((void**)&xl,  g_xl);
    cudaGetSymbolAddress((void**)&qh,  g_qh);
    cudaGetSymbolAddress((void**)&ql,  g_ql);
    cudaGetSymbolAddress((void**)&kh,  g_kh);
    cudaGetSymbolAddress((void**)&kl,  g_kl);
    cudaGetSymbolAddress((void**)&vh,  g_vh);
    cudaGetSymbolAddress((void**)&vl,  g_vl);
    cudaGetSymbolAddress((void**)&ch,  g_ch);
    cudaGetSymbolAddress((void**)&cl,  g_cl);
    cudaGetSymbolAddress((void**)&wth, g_wth);
    cudaGetSymbolAddress((void**)&wtl, g_wtl);
    const size_t WSZ = (size_t)Hsz * Hsz;

    cudaFuncSetAttribute(attn_mma, cudaFuncAttributeMaxDynamicSharedMemorySize,
                         ATTN_MMA_SMEM);
    cudaFuncSetAttribute(gemm_mma<false, true>, cudaFuncAttributeMaxDynamicSharedMemorySize,
                         GMMA_SMEM);
    cudaFuncSetAttribute(gemm_mma<true, false>, cudaFuncAttributeMaxDynamicSharedMemorySize,
                         GMMA_SMEM);

    // --- operand prep ---
    const int n4 = ROWS * Hsz / 4;
    split_f32<<<(n4 + 255) / 256, 256>>>(X, xh, xl, n4);
    dim3 wb(32, 8), wg(32, 32);
    wsplit_t<<<wg, wb>>>(Wq, wth + 0 * WSZ, wtl + 0 * WSZ);
    wsplit_t<<<wg, wb>>>(Wk, wth + 1 * WSZ, wtl + 1 * WSZ);
    wsplit_t<<<wg, wb>>>(Wv, wth + 2 * WSZ, wtl + 2 * WSZ);
    wsplit_t<<<wg, wb>>>(Wo, wth + 3 * WSZ, wtl + 3 * WSZ);

    // --- projections: emit split-bf16 directly ---
    dim3 gg(Hsz / 128, ROWS / 128);   // (8, 32)
    gemm_mma<false, true><<<gg, 256, GMMA_SMEM>>>(xh, xl, wth + 0 * WSZ, wtl + 0 * WSZ,
                                                  bq, nullptr, nullptr, qh, ql);
    gemm_mma<false, true><<<gg, 256, GMMA_SMEM>>>(xh, xl, wth + 1 * WSZ, wtl + 1 * WSZ,
                                                  bk, nullptr, nullptr, kh, kl);
    gemm_mma<false, true><<<gg, 256, GMMA_SMEM>>>(xh, xl, wth + 2 * WSZ, wtl + 2 * WSZ,
                                                  bv, nullptr, nullptr, vh, vl);

    // --- attention (bf16-split in, bf16-split out) ---
    dim3 ga(Ssz / 128, Bc * NHn);     // (8, 64)
    attn_mma<<<ga, 256, ATTN_MMA_SMEM>>>(qh, ql, kh, kl, vh, vl, ch, cl);

    // --- output projection + residual (fp32 out) ---
    gemm_mma<true, false><<<gg, 256, GMMA_SMEM>>>(ch, cl, wth + 3 * WSZ, wtl + 3 * WSZ,
                                                  bo, X, y, nullptr, nullptr);

    lnorm_cls<<<ROWS, 256>>>(y, ln_g, ln_b, Ws, bs, span);
    finalize<<<(ROWS + 255) / 256, 256>>>(span, eb, out);
}